// round 5
// baseline (speedup 1.0000x reference)
#include <cuda_runtime.h>
#include <cstdint>
#include <math.h>

#define N_STM 65536
#define N_LTM 65536
#define TOP_M 2048
#define NBIN  4096
#define TVOL  (5*96*96*96)

// scratch (static zero-init; every kernel restores its state for graph replay)
__device__ int                g_hist[NBIN];
__device__ int                g_scal[8];   // 4:n_act 5:n_stages (0,1 legacy)
__device__ int                g_sel[TOP_M];
__device__ int                g_boundary[N_STM];
__device__ float              g_Kproj[TOP_M*64];
__device__ float              g_kpT[64*TOP_M];                 // [k][m]
__device__ float              g_omega[TOP_M];
__device__ float              g_lknC[(size_t)(N_LTM+128)*64];  // compacted active lkn
__device__ unsigned           g_ajinv[N_LTM+128];              // ~orig_j per compacted row
__device__ unsigned long long g_best[TOP_M];
__device__ unsigned long long g_key[TOP_M];
__device__ int                g_unm[TOP_M];
__device__ int                g_rank[TOP_M];
__device__ int                g_free[TOP_M];
__device__ float              g_tb0[TVOL];
__device__ float              g_tb1[TVOL];

__device__ __forceinline__ unsigned fmono(float f) {
    unsigned u = __float_as_uint(f);
    return (u & 0x80000000u) ? ~u : (u | 0x80000000u);
}
__device__ __forceinline__ float funmono(unsigned m) {
    unsigned u = (m & 0x80000000u) ? (m ^ 0x80000000u) : ~m;
    return __uint_as_float(u);
}
__device__ __forceinline__ unsigned long long dup2(float x) {
    unsigned long long r; unsigned xi = __float_as_uint(x);
    asm("mov.b64 %0, {%1,%2};" : "=l"(r) : "r"(xi), "r"(xi));
    return r;
}
__device__ __forceinline__ void fma2(unsigned long long& d,
                                     unsigned long long a, unsigned long long b) {
    asm("fma.rn.f32x2 %0, %1, %2, %0;" : "+l"(d) : "l"(a), "l"(b));
}
__device__ __forceinline__ unsigned long long stm_key(int i, float h) {
    return ((unsigned long long)__float_as_uint(h) << 32) | (0xFFFFFFFFu - (unsigned)i);
}
__device__ __forceinline__ int hbin(float h) {
    return min(max((int)(h * (float)NBIN), 0), NBIN - 1);
}

// ---- 1: ltm_K normalize + active compaction  |  stm histogram -------------
__global__ void k_histlkn(const float* __restrict__ ltm_K, const int* __restrict__ ltm_act,
                          const float* __restrict__ stm_h, const int* __restrict__ stm_act) {
    __shared__ float part[8];
    __shared__ int sact[4];
    __shared__ int sbase;
    int tid = threadIdx.x;
    int g = tid >> 6, c = tid & 63, wid = tid >> 5, lane = tid & 31;
    int j = blockIdx.x * 4 + g;
    float v = ltm_K[(size_t)j * 64 + c];
    float sq = v * v;
    #pragma unroll
    for (int off = 16; off; off >>= 1) sq += __shfl_xor_sync(0xFFFFFFFFu, sq, off);
    if (lane == 0) part[wid] = sq;
    int a = (ltm_act[j] > 0) ? 1 : 0;
    if (c == 0) sact[g] = a;
    __syncthreads();
    if (tid == 0) {
        int tot = sact[0] + sact[1] + sact[2] + sact[3];
        sbase = tot ? atomicAdd(&g_scal[4], tot) : 0;
    }
    __syncthreads();
    if (a) {
        int off = 0;
        #pragma unroll
        for (int x = 0; x < 4; ++x) if (x < g) off += sact[x];
        int pos = sbase + off;
        float tot = part[g * 2] + part[g * 2 + 1];
        g_lknC[(size_t)pos * 64 + c] = v / (sqrtf(tot) + 1e-8f);
        if (c == 0) g_ajinv[pos] = 0xFFFFFFFFu - (unsigned)j;
    }
    int i = blockIdx.x * 256 + tid;
    if (i < N_STM && stm_act[i] > 0) atomicAdd(&g_hist[hbin(stm_h[i])], 1);
}

// ---- 2: merged threshold + pad + top-M compaction + tie-break (1 block) ----
__global__ void k_prep(const float* __restrict__ fat, float* __restrict__ oF,
                       const float* __restrict__ h, const int* __restrict__ act) {
    __shared__ int s[1024];
    __shared__ int sT, sCnt, ssel, sbnd;
    int t = threadIdx.x;
    int base = NBIN - 1 - 4 * t;
    int h0 = g_hist[base], h1 = g_hist[base-1], h2 = g_hist[base-2], h3 = g_hist[base-3];
    g_hist[base] = 0; g_hist[base-1] = 0; g_hist[base-2] = 0; g_hist[base-3] = 0;
    int sum = h0 + h1 + h2 + h3;
    s[t] = sum;
    if (t == 0) { ssel = 0; sbnd = 0; }
    __syncthreads();
    for (int off = 1; off < 1024; off <<= 1) {
        int v = s[t], a2 = (t >= off) ? s[t - off] : 0;
        __syncthreads(); s[t] = v + a2; __syncthreads();
    }
    int c = s[t] - sum;
    int hh[4] = {h0, h1, h2, h3};
    #pragma unroll
    for (int q = 0; q < 4; ++q) {
        if (c < TOP_M && c + hh[q] >= TOP_M) { sT = base - q; sCnt = c; }
        c += hh[q];
    }
    // pad compacted lkn tail + misc init
    int n_act = g_scal[4];
    for (int idx = t; idx < 128 * 64; idx += 1024)
        g_lknC[(size_t)(n_act + (idx >> 6)) * 64 + (idx & 63)] = 0.0f;
    if (t < 128) g_ajinv[n_act + t] = 0u;
    if (t == 0) {
        g_scal[5] = (n_act + 127) >> 7;
        oF[0] = 0.2f * fat[0];
    }
    __syncthreads();
    int T = sT;
    for (int i = t; i < N_STM; i += 1024) {
        if (act[i] > 0) {
            int b = hbin(h[i]);
            if (b > T)       g_sel[atomicAdd(&ssel, 1)] = i;
            else if (b == T) g_boundary[atomicAdd(&sbnd, 1)] = i;
        }
    }
    __syncthreads();
    int B = sbnd, need = TOP_M - sCnt;
    for (int cc = t; cc < B; cc += 1024) {
        int i = g_boundary[cc];
        unsigned long long k = stm_key(i, h[i]);
        int r = 0;
        for (int q = 0; q < B; ++q) {
            int i2 = g_boundary[q];
            r += (stm_key(i2, h[i2]) > k);
        }
        if (r < need) g_sel[atomicAdd(&ssel, 1)] = i;
    }
    __syncthreads();
    if (t == 0) g_scal[4] = 0;   // restore for graph replay
}

// ---- 3: projection + kp normalize (writes transposed kpT) ------------------
__global__ void k_proj(const float* __restrict__ stm_K, const float* __restrict__ stm_h,
                       const float* __restrict__ W, const float* __restrict__ b) {
    int m = blockIdx.x, c = threadIdx.x;
    __shared__ float sK[16];
    __shared__ float ws[2];
    int s = g_sel[m];
    if (c < 16) sK[c] = stm_K[(size_t)s * 16 + c];
    __syncthreads();
    float acc = b[c];
    #pragma unroll
    for (int k = 0; k < 16; ++k) acc = fmaf(sK[k], W[k * 64 + c], acc);
    float sq = acc * acc;
    #pragma unroll
    for (int off = 16; off; off >>= 1) sq += __shfl_xor_sync(0xFFFFFFFFu, sq, off);
    if ((c & 31) == 0) ws[c >> 5] = sq;
    __syncthreads();
    g_Kproj[m * 64 + c] = acc;
    g_kpT[c * TOP_M + m] = acc / (sqrtf(ws[0] + ws[1]) + 1e-8f);
    if (c == 0) g_omega[m] = 0.05f * stm_h[s];
}

// ---- 4: fused sims GEMM + argmax, software-pipelined tiles -----------------
// CTA 64m x 128j, thread tile 8m(4x f32x2) x 4j. kp_s[k][64m], lk_s[j][65].
#define SIMS_SMEM ((64*64 + 128*65 + 128) * 4)  // 50176 B
__global__ void __launch_bounds__(256, 2) k_sims() {
    extern __shared__ float sm[];
    float* kp_s = sm;                      // [k][64]
    float* lk_s = sm + 64 * 64;            // [j][65]
    unsigned* jinv_s = (unsigned*)(sm + 64 * 64 + 128 * 65);
    const int tid = threadIdx.x;
    const int mb = tid >> 5;
    const int jb = tid & 31;
    const int m0 = blockIdx.x * 64;
    const int ns = g_scal[5];

    for (int idx = tid; idx < 4096; idx += 256) {
        int m = idx & 63, k = idx >> 6;
        kp_s[k * 64 + m] = g_kpT[k * TOP_M + m0 + m];
    }

    unsigned long long run[8];
    #pragma unroll
    for (int i = 0; i < 8; ++i) run[i] = 0ull;

    int s = blockIdx.y;
    float4 pre[8];
    unsigned pj = 0;
    {   // prefetch first tile
        int j0 = s * 128;
        #pragma unroll
        for (int it = 0; it < 8; ++it) {
            int idx = tid + it * 256;
            pre[it] = reinterpret_cast<const float4*>(g_lknC)
                          [(size_t)(j0 + (idx >> 4)) * 16 + (idx & 15)];
        }
        if (tid < 128) pj = g_ajinv[j0 + tid];
    }

    for (; s < ns; ) {
        __syncthreads();   // previous compute (or kp fill) done
        #pragma unroll
        for (int it = 0; it < 8; ++it) {
            int idx = tid + it * 256;
            float* dst = &lk_s[(idx >> 4) * 65 + (idx & 15) * 4];
            dst[0] = pre[it].x; dst[1] = pre[it].y; dst[2] = pre[it].z; dst[3] = pre[it].w;
        }
        if (tid < 128) jinv_s[tid] = pj;
        __syncthreads();

        int snext = s + gridDim.y;
        if (snext < ns) {   // prefetch next tile during compute
            int j0 = snext * 128;
            #pragma unroll
            for (int it = 0; it < 8; ++it) {
                int idx = tid + it * 256;
                pre[it] = reinterpret_cast<const float4*>(g_lknC)
                              [(size_t)(j0 + (idx >> 4)) * 16 + (idx & 15)];
            }
            if (tid < 128) pj = g_ajinv[j0 + tid];
        }

        unsigned long long acc[4][4];
        #pragma unroll
        for (int a = 0; a < 4; ++a)
            #pragma unroll
            for (int q = 0; q < 4; ++q) acc[a][q] = 0ull;

        #pragma unroll 8
        for (int k = 0; k < 64; ++k) {
            const unsigned long long* ap =
                reinterpret_cast<const unsigned long long*>(&kp_s[k * 64 + mb * 8]);
            unsigned long long a0 = ap[0], a1 = ap[1], a2 = ap[2], a3 = ap[3];
            #pragma unroll
            for (int q = 0; q < 4; ++q) {
                unsigned long long b2 = dup2(lk_s[(jb + q * 32) * 65 + k]);
                fma2(acc[0][q], a0, b2);
                fma2(acc[1][q], a1, b2);
                fma2(acc[2][q], a2, b2);
                fma2(acc[3][q], a3, b2);
            }
        }

        int j0 = s * 128;
        (void)j0;
        #pragma unroll
        for (int mp = 0; mp < 4; ++mp) {
            #pragma unroll
            for (int q = 0; q < 4; ++q) {
                unsigned lo = (unsigned)(acc[mp][q] & 0xFFFFFFFFull);
                unsigned hi = (unsigned)(acc[mp][q] >> 32);
                unsigned jinv = jinv_s[jb + q * 32];
                unsigned long long pl =
                    ((unsigned long long)fmono(__uint_as_float(lo)) << 32) | jinv;
                unsigned long long ph =
                    ((unsigned long long)fmono(__uint_as_float(hi)) << 32) | jinv;
                if (pl > run[2 * mp])     run[2 * mp]     = pl;
                if (ph > run[2 * mp + 1]) run[2 * mp + 1] = ph;
            }
        }
        s = snext;
    }

    #pragma unroll
    for (int i = 0; i < 8; ++i) {
        #pragma unroll
        for (int off = 16; off; off >>= 1) {
            unsigned long long o = __shfl_xor_sync(0xFFFFFFFFu, run[i], off);
            if (o > run[i]) run[i] = o;
        }
        if (jb == 0) atomicMax(&g_best[m0 + mb * 8 + i], run[i]);
    }
}

// ---- 5: stm_V norm clip -----------------------------------------------------
__global__ void k_stmv(const float* __restrict__ stm_V, float* __restrict__ oSV) {
    int w = threadIdx.x >> 5, lane = threadIdx.x & 31;
    size_t row = (size_t)blockIdx.x * 8 + w;
    float4 v = reinterpret_cast<const float4*>(stm_V)[row * 32 + lane];
    float sq = v.x*v.x + v.y*v.y + v.z*v.z + v.w*v.w;
    #pragma unroll
    for (int off = 16; off; off >>= 1) sq += __shfl_xor_sync(0xFFFFFFFFu, sq, off);
    float sc = fminf(1.0f, 2.0f / (sqrtf(sq) + 1e-8f));
    reinterpret_cast<float4*>(oSV)[row * 32 + lane] =
        make_float4(v.x*sc, v.y*sc, v.z*sc, v.w*sc);
}

// ---- 6: first TOP_M inactive slots (ascending) ------------------------------
__global__ void k_freeslots(const int* __restrict__ act) {
    __shared__ int sc[1024];
    int t = threadIdx.x, base = t * 64, cnt = 0;
    #pragma unroll 8
    for (int i = 0; i < 64; ++i) cnt += (act[base + i] == 0);
    sc[t] = cnt;
    __syncthreads();
    for (int off = 1; off < 1024; off <<= 1) {
        int v = sc[t], a = (t >= off) ? sc[t - off] : 0;
        __syncthreads(); sc[t] = v + a; __syncthreads();
    }
    int p = sc[t] - cnt;
    for (int i = 0; i < 64; ++i)
        if (act[base + i] == 0) { if (p < TOP_M) g_free[p] = base + i; ++p; }
}

// ---- 7: matched scatter-add (+ restore g_best for replay) ------------------
__global__ void k_matched(const float* __restrict__ stm_V, const float* __restrict__ stm_e,
                          const float* __restrict__ stm_h,
                          float* __restrict__ oK, float* __restrict__ oV,
                          float* __restrict__ oe, float* __restrict__ oh) {
    int m = blockIdx.x, c = threadIdx.x;
    __shared__ unsigned long long sp;
    if (c == 0) { sp = g_best[m]; g_best[m] = 0ull; }
    __syncthreads();
    unsigned long long p = sp;
    float sim = funmono((unsigned)(p >> 32));
    int j = (int)(0xFFFFFFFFu - (unsigned)(p & 0xFFFFFFFFull));
    bool matched = (sim >= 0.5f);
    int s = g_sel[m];
    float om = g_omega[m];
    if (c == 0) {
        g_unm[m] = matched ? 0 : 1;
        g_key[m] = stm_key(s, stm_h[s]);
        if (matched) atomicAdd(&oh[j], om);
    }
    if (matched) {
        atomicAdd(&oK[(size_t)j * 64 + c], om * g_Kproj[m * 64 + c]);
        atomicAdd(&oV[(size_t)j * 128 + c], om * stm_V[(size_t)s * 128 + c]);
        atomicAdd(&oV[(size_t)j * 128 + 64 + c], om * stm_V[(size_t)s * 128 + 64 + c]);
        if (c < 4) atomicAdd(&oe[(size_t)j * 4 + c], om * stm_e[(size_t)s * 4 + c]);
    }
}

// ---- 8: rank unmatched (h desc, idx asc — matches jax stable order) ---------
__global__ void k_rank() {
    __shared__ unsigned long long sk[TOP_M];
    __shared__ unsigned char su[TOP_M];
    int t = threadIdx.x;
    for (int i = t; i < TOP_M; i += 256) { sk[i] = g_key[i]; su[i] = (unsigned char)g_unm[i]; }
    __syncthreads();
    int m = blockIdx.x * 256 + t;
    if (g_unm[m]) {
        unsigned long long k = sk[m];
        int r = 0;
        for (int i = 0; i < TOP_M; ++i) r += (su[i] && sk[i] > k);
        g_rank[m] = r;
    }
}

// ---- 9: unmatched fresh-slot writes -----------------------------------------
__global__ void k_unmatch(const float* __restrict__ stm_V, const float* __restrict__ stm_e,
                          float* __restrict__ oK, float* __restrict__ oV,
                          float* __restrict__ oe, float* __restrict__ oh) {
    int m = blockIdx.x;
    if (!g_unm[m]) return;
    int slot = g_free[g_rank[m]], c = threadIdx.x, s = g_sel[m];
    oK[(size_t)slot * 64 + c] = g_Kproj[m * 64 + c];
    oV[(size_t)slot * 128 + c] = stm_V[(size_t)s * 128 + c];
    oV[(size_t)slot * 128 + 64 + c] = stm_V[(size_t)s * 128 + 64 + c];
    if (c < 4) oe[(size_t)slot * 4 + c] = stm_e[(size_t)s * 4 + c];
    if (c == 0) oh[slot] = g_omega[m];
}

// ---- gaussian blur ------------------------------------------------------------
__device__ __forceinline__ void gw(float* w, float& inv) {
    w[0] = 1.0f; float sum = 1.0f;
    #pragma unroll
    for (int i = 1; i < 7; ++i) {
        w[i] = expf(-0.5f * (float)(i * i) / 4.0f);
        sum += 2.0f * w[i];
    }
    inv = 1.0f / sum;
}
__global__ void k_blur(const float* __restrict__ in, float* __restrict__ outp, int stride) {
    float w[7], inv; gw(w, inv);
    int idx = blockIdx.x * blockDim.x + threadIdx.x;
    if (idx >= TVOL) return;
    int x = (idx / stride) % 96;
    float acc = in[idx] * w[0];
    #pragma unroll
    for (int t = 1; t < 7; ++t) {
        float a = (x - t >= 0) ? in[idx - t * stride] : 0.0f;
        float b = (x + t < 96) ? in[idx + t * stride] : 0.0f;
        acc += (a + b) * w[t];
    }
    outp[idx] = acc * inv;
}
__global__ void k_blur_merge(const float* __restrict__ in, const float* __restrict__ ltm_t,
                             float* __restrict__ oT) {
    float w[7], inv; gw(w, inv);
    int idx = blockIdx.x * blockDim.x + threadIdx.x;
    if (idx >= TVOL) return;
    int x = idx % 96;
    float acc = in[idx] * w[0];
    #pragma unroll
    for (int t = 1; t < 7; ++t) {
        float a = (x - t >= 0) ? in[idx - t] : 0.0f;
        float b = (x + t < 96) ? in[idx + t] : 0.0f;
        acc += (a + b) * w[t];
    }
    float xi = (idx < 96 * 96 * 96) ? 0.005f : 0.003f;
    oT[idx] = ltm_t[idx] + xi * (acc * inv);
}

extern "C" void kernel_launch(void* const* d_in, const int* in_sizes, int n_in,
                              void* d_out, int out_size) {
    (void)in_sizes; (void)n_in; (void)out_size;
    const float* stm_K   = (const float*)d_in[0];
    const float* stm_V   = (const float*)d_in[1];
    const float* stm_e   = (const float*)d_in[2];
    const float* stm_h   = (const float*)d_in[3];
    const float* ltm_K   = (const float*)d_in[4];
    const float* ltm_V   = (const float*)d_in[5];
    const float* ltm_e   = (const float*)d_in[6];
    const float* ltm_h   = (const float*)d_in[7];
    const float* W       = (const float*)d_in[8];
    const float* b       = (const float*)d_in[9];
    const float* stm_t   = (const float*)d_in[10];
    const float* ltm_t   = (const float*)d_in[11];
    const float* fatigue = (const float*)d_in[12];
    const int*   stm_act = (const int*)d_in[13];
    const int*   ltm_act = (const int*)d_in[14];

    float* out = (float*)d_out;
    float* oK  = out;                 // 65536*64
    float* oV  = out + 4194304;       // 65536*128
    float* oe  = out + 12582912;      // 65536*4
    float* oh  = out + 12845056;      // 65536
    float* oSV = out + 12910592;      // 65536*128
    float* oT  = out + 21299200;      // 5*96^3
    float* oF  = out + 25722880;      // 1

    static bool attr_set = false;
    if (!attr_set) {
        cudaFuncSetAttribute(k_sims, cudaFuncAttributeMaxDynamicSharedMemorySize, SIMS_SMEM);
        attr_set = true;
    }

    // order chosen so k_sims is kernel launch #4 (ncu sample index)
    k_histlkn<<<16384, 256>>>(ltm_K, ltm_act, stm_h, stm_act);
    k_prep<<<1, 1024>>>(fatigue, oF, stm_h, stm_act);
    k_proj<<<2048, 64>>>(stm_K, stm_h, W, b);
    k_sims<<<dim3(32, 9), 256, SIMS_SMEM>>>();

    k_stmv<<<8192, 256>>>(stm_V, oSV);
    k_freeslots<<<1, 1024>>>(ltm_act);

    cudaMemcpyAsync(oK, ltm_K, (size_t)4194304 * 4, cudaMemcpyDeviceToDevice, 0);
    cudaMemcpyAsync(oV, ltm_V, (size_t)8388608 * 4, cudaMemcpyDeviceToDevice, 0);
    cudaMemcpyAsync(oe, ltm_e, (size_t)262144 * 4, cudaMemcpyDeviceToDevice, 0);
    cudaMemcpyAsync(oh, ltm_h, (size_t)65536 * 4, cudaMemcpyDeviceToDevice, 0);

    k_matched<<<2048, 64>>>(stm_V, stm_e, stm_h, oK, oV, oe, oh);
    k_rank<<<8, 256>>>();
    k_unmatch<<<2048, 64>>>(stm_V, stm_e, oK, oV, oe, oh);

    int tb = (TVOL + 255) / 256;
    k_blur<<<tb, 256>>>(stm_t, g_tb0, 96 * 96);   // axis D
    k_blur<<<tb, 256>>>(g_tb0, g_tb1, 96);        // axis H
    k_blur_merge<<<tb, 256>>>(g_tb1, ltm_t, oT);  // axis W + merge
}

// round 6
// speedup vs baseline: 1.1462x; 1.1462x over previous
#include <cuda_runtime.h>
#include <cstdint>
#include <math.h>

#define N_STM 65536
#define N_LTM 65536
#define TOP_M 2048
#define NBIN  4096
#define TVOL  (5*96*96*96)

// scratch (static zero-init; every kernel restores its state for graph replay)
__device__ int                g_hist[NBIN];
__device__ int                g_scal[8];   // 4:n_act 5:n_stages
__device__ int                g_sel[TOP_M];
__device__ int                g_boundary[N_STM];
__device__ float              g_Kproj[TOP_M*64];
__device__ float              g_kpT[64*TOP_M];                 // [k][m]
__device__ float              g_omega[TOP_M];
__device__ float              g_lknC[(size_t)(N_LTM+128)*64];  // compacted active lkn
__device__ unsigned           g_ajinv[N_LTM+128];              // ~orig_j per compacted row
__device__ unsigned long long g_best[TOP_M];
__device__ unsigned long long g_key[TOP_M];
__device__ int                g_unm[TOP_M];
__device__ int                g_rank[TOP_M];
__device__ int                g_free[TOP_M];
__device__ float              g_tb0[TVOL];
__device__ float              g_tb1[TVOL];

__device__ __forceinline__ unsigned fmono(float f) {
    unsigned u = __float_as_uint(f);
    return (u & 0x80000000u) ? ~u : (u | 0x80000000u);
}
__device__ __forceinline__ float funmono(unsigned m) {
    unsigned u = (m & 0x80000000u) ? (m ^ 0x80000000u) : ~m;
    return __uint_as_float(u);
}
__device__ __forceinline__ unsigned long long dup2(float x) {
    unsigned long long r; unsigned xi = __float_as_uint(x);
    asm("mov.b64 %0, {%1,%2};" : "=l"(r) : "r"(xi), "r"(xi));
    return r;
}
__device__ __forceinline__ void fma2(unsigned long long& d,
                                     unsigned long long a, unsigned long long b) {
    asm("fma.rn.f32x2 %0, %1, %2, %0;" : "+l"(d) : "l"(a), "l"(b));
}
__device__ __forceinline__ unsigned long long stm_key(int i, float h) {
    return ((unsigned long long)__float_as_uint(h) << 32) | (0xFFFFFFFFu - (unsigned)i);
}
__device__ __forceinline__ int hbin(float h) {
    return min(max((int)(h * (float)NBIN), 0), NBIN - 1);
}

// ---- base-state copy: ltm {K,V,e,h} -> contiguous head of d_out -----------
__global__ void k_copy(const float4* __restrict__ K, const float4* __restrict__ V,
                       const float4* __restrict__ e, const float4* __restrict__ h,
                       float4* __restrict__ out) {
    int i = blockIdx.x * blockDim.x + threadIdx.x;   // 3227648 total
    float4 v;
    if (i < 1048576)       v = K[i];
    else if (i < 3145728)  v = V[i - 1048576];
    else if (i < 3211264)  v = e[i - 3145728];
    else                   v = h[i - 3211264];
    out[i] = v;
}

// ---- 1: ltm_K normalize + active compaction  |  stm histogram -------------
__global__ void k_histlkn(const float* __restrict__ ltm_K, const int* __restrict__ ltm_act,
                          const float* __restrict__ stm_h, const int* __restrict__ stm_act) {
    __shared__ float part[8];
    __shared__ int sact[4];
    __shared__ int sbase;
    int tid = threadIdx.x;
    int g = tid >> 6, c = tid & 63, wid = tid >> 5, lane = tid & 31;
    int j = blockIdx.x * 4 + g;
    float v = ltm_K[(size_t)j * 64 + c];
    float sq = v * v;
    #pragma unroll
    for (int off = 16; off; off >>= 1) sq += __shfl_xor_sync(0xFFFFFFFFu, sq, off);
    if (lane == 0) part[wid] = sq;
    int a = (ltm_act[j] > 0) ? 1 : 0;
    if (c == 0) sact[g] = a;
    __syncthreads();
    if (tid == 0) {
        int tot = sact[0] + sact[1] + sact[2] + sact[3];
        sbase = tot ? atomicAdd(&g_scal[4], tot) : 0;
    }
    __syncthreads();
    if (a) {
        int off = 0;
        #pragma unroll
        for (int x = 0; x < 4; ++x) if (x < g) off += sact[x];
        int pos = sbase + off;
        float tot = part[g * 2] + part[g * 2 + 1];
        g_lknC[(size_t)pos * 64 + c] = v / (sqrtf(tot) + 1e-8f);
        if (c == 0) g_ajinv[pos] = 0xFFFFFFFFu - (unsigned)j;
    }
    int i = blockIdx.x * 256 + tid;
    if (i < N_STM && stm_act[i] > 0) atomicAdd(&g_hist[hbin(stm_h[i])], 1);
}

// ---- 2: merged threshold + pad + top-M compaction + tie-break (1 block) ----
__global__ void k_prep(const float* __restrict__ fat, float* __restrict__ oF,
                       const float* __restrict__ h, const int* __restrict__ act) {
    __shared__ int s[1024];
    __shared__ int sT, sCnt, ssel, sbnd;
    int t = threadIdx.x;
    int base = NBIN - 1 - 4 * t;
    int h0 = g_hist[base], h1 = g_hist[base-1], h2 = g_hist[base-2], h3 = g_hist[base-3];
    g_hist[base] = 0; g_hist[base-1] = 0; g_hist[base-2] = 0; g_hist[base-3] = 0;
    int sum = h0 + h1 + h2 + h3;
    s[t] = sum;
    if (t == 0) { ssel = 0; sbnd = 0; }
    __syncthreads();
    for (int off = 1; off < 1024; off <<= 1) {
        int v = s[t], a2 = (t >= off) ? s[t - off] : 0;
        __syncthreads(); s[t] = v + a2; __syncthreads();
    }
    int c = s[t] - sum;
    int hh[4] = {h0, h1, h2, h3};
    #pragma unroll
    for (int q = 0; q < 4; ++q) {
        if (c < TOP_M && c + hh[q] >= TOP_M) { sT = base - q; sCnt = c; }
        c += hh[q];
    }
    // pad compacted lkn tail + misc init
    int n_act = g_scal[4];
    for (int idx = t; idx < 128 * 64; idx += 1024)
        g_lknC[(size_t)(n_act + (idx >> 6)) * 64 + (idx & 63)] = 0.0f;
    if (t < 128) g_ajinv[n_act + t] = 0u;
    if (t == 0) {
        g_scal[5] = (n_act + 127) >> 7;
        oF[0] = 0.2f * fat[0];
    }
    __syncthreads();
    int T = sT;
    for (int b2 = 0; b2 < N_STM; b2 += 4096) {
        int ia[4]; float ha[4];
        #pragma unroll
        for (int q = 0; q < 4; ++q) {
            int i = b2 + q * 1024 + t;
            ia[q] = act[i]; ha[q] = h[i];
        }
        #pragma unroll
        for (int q = 0; q < 4; ++q) {
            if (ia[q] > 0) {
                int bn = hbin(ha[q]);
                int i = b2 + q * 1024 + t;
                if (bn > T)       g_sel[atomicAdd(&ssel, 1)] = i;
                else if (bn == T) g_boundary[atomicAdd(&sbnd, 1)] = i;
            }
        }
    }
    __syncthreads();
    int B = sbnd, need = TOP_M - sCnt;
    for (int cc = t; cc < B; cc += 1024) {
        int i = g_boundary[cc];
        unsigned long long k = stm_key(i, h[i]);
        int r = 0;
        for (int q = 0; q < B; ++q) {
            int i2 = g_boundary[q];
            r += (stm_key(i2, h[i2]) > k);
        }
        if (r < need) g_sel[atomicAdd(&ssel, 1)] = i;
    }
    __syncthreads();
    if (t == 0) g_scal[4] = 0;   // restore for graph replay
}

// ---- 3: projection + kp normalize (writes transposed kpT) ------------------
__global__ void k_proj(const float* __restrict__ stm_K, const float* __restrict__ stm_h,
                       const float* __restrict__ W, const float* __restrict__ b) {
    int m = blockIdx.x, c = threadIdx.x;
    __shared__ float sK[16];
    __shared__ float ws[2];
    int s = g_sel[m];
    if (c < 16) sK[c] = stm_K[(size_t)s * 16 + c];
    __syncthreads();
    float acc = b[c];
    #pragma unroll
    for (int k = 0; k < 16; ++k) acc = fmaf(sK[k], W[k * 64 + c], acc);
    float sq = acc * acc;
    #pragma unroll
    for (int off = 16; off; off >>= 1) sq += __shfl_xor_sync(0xFFFFFFFFu, sq, off);
    if ((c & 31) == 0) ws[c >> 5] = sq;
    __syncthreads();
    g_Kproj[m * 64 + c] = acc;
    g_kpT[c * TOP_M + m] = acc / (sqrtf(ws[0] + ws[1]) + 1e-8f);
    if (c == 0) g_omega[m] = 0.05f * stm_h[s];
}

// ---- 4: fused sims GEMM + argmax, software-pipelined tiles -----------------
#define SIMS_SMEM ((64*64 + 128*65 + 128) * 4)  // 50176 B
__global__ void __launch_bounds__(256, 2) k_sims() {
    extern __shared__ float sm[];
    float* kp_s = sm;                      // [k][64]
    float* lk_s = sm + 64 * 64;            // [j][65]
    unsigned* jinv_s = (unsigned*)(sm + 64 * 64 + 128 * 65);
    const int tid = threadIdx.x;
    const int mb = tid >> 5;
    const int jb = tid & 31;
    const int m0 = blockIdx.x * 64;
    const int ns = g_scal[5];

    for (int idx = tid; idx < 4096; idx += 256) {
        int m = idx & 63, k = idx >> 6;
        kp_s[k * 64 + m] = g_kpT[k * TOP_M + m0 + m];
    }

    unsigned long long run[8];
    #pragma unroll
    for (int i = 0; i < 8; ++i) run[i] = 0ull;

    int s = blockIdx.y;
    float4 pre[8];
    unsigned pj = 0;
    {
        int j0 = s * 128;
        #pragma unroll
        for (int it = 0; it < 8; ++it) {
            int idx = tid + it * 256;
            pre[it] = reinterpret_cast<const float4*>(g_lknC)
                          [(size_t)(j0 + (idx >> 4)) * 16 + (idx & 15)];
        }
        if (tid < 128) pj = g_ajinv[j0 + tid];
    }

    for (; s < ns; ) {
        __syncthreads();
        #pragma unroll
        for (int it = 0; it < 8; ++it) {
            int idx = tid + it * 256;
            float* dst = &lk_s[(idx >> 4) * 65 + (idx & 15) * 4];
            dst[0] = pre[it].x; dst[1] = pre[it].y; dst[2] = pre[it].z; dst[3] = pre[it].w;
        }
        if (tid < 128) jinv_s[tid] = pj;
        __syncthreads();

        int snext = s + gridDim.y;
        if (snext < ns) {
            int j0 = snext * 128;
            #pragma unroll
            for (int it = 0; it < 8; ++it) {
                int idx = tid + it * 256;
                pre[it] = reinterpret_cast<const float4*>(g_lknC)
                              [(size_t)(j0 + (idx >> 4)) * 16 + (idx & 15)];
            }
            if (tid < 128) pj = g_ajinv[j0 + tid];
        }

        unsigned long long acc[4][4];
        #pragma unroll
        for (int a = 0; a < 4; ++a)
            #pragma unroll
            for (int q = 0; q < 4; ++q) acc[a][q] = 0ull;

        #pragma unroll 8
        for (int k = 0; k < 64; ++k) {
            const unsigned long long* ap =
                reinterpret_cast<const unsigned long long*>(&kp_s[k * 64 + mb * 8]);
            unsigned long long a0 = ap[0], a1 = ap[1], a2 = ap[2], a3 = ap[3];
            #pragma unroll
            for (int q = 0; q < 4; ++q) {
                unsigned long long b2 = dup2(lk_s[(jb + q * 32) * 65 + k]);
                fma2(acc[0][q], a0, b2);
                fma2(acc[1][q], a1, b2);
                fma2(acc[2][q], a2, b2);
                fma2(acc[3][q], a3, b2);
            }
        }

        #pragma unroll
        for (int mp = 0; mp < 4; ++mp) {
            #pragma unroll
            for (int q = 0; q < 4; ++q) {
                unsigned lo = (unsigned)(acc[mp][q] & 0xFFFFFFFFull);
                unsigned hi = (unsigned)(acc[mp][q] >> 32);
                unsigned jinv = jinv_s[jb + q * 32];
                unsigned long long pl =
                    ((unsigned long long)fmono(__uint_as_float(lo)) << 32) | jinv;
                unsigned long long ph =
                    ((unsigned long long)fmono(__uint_as_float(hi)) << 32) | jinv;
                if (pl > run[2 * mp])     run[2 * mp]     = pl;
                if (ph > run[2 * mp + 1]) run[2 * mp + 1] = ph;
            }
        }
        s = snext;
    }

    #pragma unroll
    for (int i = 0; i < 8; ++i) {
        #pragma unroll
        for (int off = 16; off; off >>= 1) {
            unsigned long long o = __shfl_xor_sync(0xFFFFFFFFu, run[i], off);
            if (o > run[i]) run[i] = o;
        }
        if (jb == 0) atomicMax(&g_best[m0 + mb * 8 + i], run[i]);
    }
}

// ---- 5: stm_V norm clip -----------------------------------------------------
__global__ void k_stmv(const float* __restrict__ stm_V, float* __restrict__ oSV) {
    int w = threadIdx.x >> 5, lane = threadIdx.x & 31;
    size_t row = (size_t)blockIdx.x * 8 + w;
    float4 v = reinterpret_cast<const float4*>(stm_V)[row * 32 + lane];
    float sq = v.x*v.x + v.y*v.y + v.z*v.z + v.w*v.w;
    #pragma unroll
    for (int off = 16; off; off >>= 1) sq += __shfl_xor_sync(0xFFFFFFFFu, sq, off);
    float sc = fminf(1.0f, 2.0f / (sqrtf(sq) + 1e-8f));
    reinterpret_cast<float4*>(oSV)[row * 32 + lane] =
        make_float4(v.x*sc, v.y*sc, v.z*sc, v.w*sc);
}

// ---- 6: first TOP_M inactive slots (coalesced ballot scan, early exit) ------
__global__ void k_freeslots(const int* __restrict__ act) {
    int t = threadIdx.x, w = t >> 5, lane = t & 31;
    __shared__ int wcnt[32];
    int running = 0;
    for (int tile = 0; tile < 64 && running < TOP_M; ++tile) {
        int i = tile * 1024 + t;
        int inact = (act[i] == 0);
        unsigned bal = __ballot_sync(0xFFFFFFFFu, inact);
        if (lane == 0) wcnt[w] = __popc(bal);
        __syncthreads();
        int pre = 0, total = 0;
        #pragma unroll
        for (int x = 0; x < 32; ++x) {
            int cx = wcnt[x];
            if (x < w) pre += cx;
            total += cx;
        }
        int pos = running + pre + __popc(bal & ((1u << lane) - 1));
        if (inact && pos < TOP_M) g_free[pos] = i;
        running += total;
        __syncthreads();
    }
}

// ---- 7: matched scatter-add (+ restore g_best for replay) ------------------
__global__ void k_matched(const float* __restrict__ stm_V, const float* __restrict__ stm_e,
                          const float* __restrict__ stm_h,
                          float* __restrict__ oK, float* __restrict__ oV,
                          float* __restrict__ oe, float* __restrict__ oh) {
    int m = blockIdx.x, c = threadIdx.x;
    __shared__ unsigned long long sp;
    if (c == 0) { sp = g_best[m]; g_best[m] = 0ull; }
    __syncthreads();
    unsigned long long p = sp;
    float sim = funmono((unsigned)(p >> 32));
    int j = (int)(0xFFFFFFFFu - (unsigned)(p & 0xFFFFFFFFull));
    bool matched = (sim >= 0.5f);
    int s = g_sel[m];
    float om = g_omega[m];
    if (c == 0) {
        g_unm[m] = matched ? 0 : 1;
        g_key[m] = stm_key(s, stm_h[s]);
        if (matched) atomicAdd(&oh[j], om);
    }
    if (matched) {
        atomicAdd(&oK[(size_t)j * 64 + c], om * g_Kproj[m * 64 + c]);
        atomicAdd(&oV[(size_t)j * 128 + c], om * stm_V[(size_t)s * 128 + c]);
        atomicAdd(&oV[(size_t)j * 128 + 64 + c], om * stm_V[(size_t)s * 128 + 64 + c]);
        if (c < 4) atomicAdd(&oe[(size_t)j * 4 + c], om * stm_e[(size_t)s * 4 + c]);
    }
}

// ---- 8: rank unmatched (h desc, idx asc) -------------------------------------
__global__ void k_rank() {
    __shared__ unsigned long long sk[TOP_M];
    __shared__ unsigned char su[TOP_M];
    int t = threadIdx.x;
    for (int i = t; i < TOP_M; i += 256) { sk[i] = g_key[i]; su[i] = (unsigned char)g_unm[i]; }
    __syncthreads();
    int m = blockIdx.x * 256 + t;
    if (g_unm[m]) {
        unsigned long long k = sk[m];
        int r = 0;
        for (int i = 0; i < TOP_M; ++i) r += (su[i] && sk[i] > k);
        g_rank[m] = r;
    }
}

// ---- 9: unmatched fresh-slot writes -------------------------------------------
__global__ void k_unmatch(const float* __restrict__ stm_V, const float* __restrict__ stm_e,
                          float* __restrict__ oK, float* __restrict__ oV,
                          float* __restrict__ oe, float* __restrict__ oh) {
    int m = blockIdx.x;
    if (!g_unm[m]) return;
    int slot = g_free[g_rank[m]], c = threadIdx.x, s = g_sel[m];
    oK[(size_t)slot * 64 + c] = g_Kproj[m * 64 + c];
    oV[(size_t)slot * 128 + c] = stm_V[(size_t)s * 128 + c];
    oV[(size_t)slot * 128 + 64 + c] = stm_V[(size_t)s * 128 + 64 + c];
    if (c < 4) oe[(size_t)slot * 4 + c] = stm_e[(size_t)s * 4 + c];
    if (c == 0) oh[slot] = g_omega[m];
}

// ---- gaussian blur --------------------------------------------------------------
__device__ __forceinline__ void gw(float* w, float& inv) {
    w[0] = 1.0f; float sum = 1.0f;
    #pragma unroll
    for (int i = 1; i < 7; ++i) {
        w[i] = expf(-0.5f * (float)(i * i) / 4.0f);
        sum += 2.0f * w[i];
    }
    inv = 1.0f / sum;
}
__global__ void k_blur(const float* __restrict__ in, float* __restrict__ outp, int stride) {
    float w[7], inv; gw(w, inv);
    int idx = blockIdx.x * blockDim.x + threadIdx.x;
    if (idx >= TVOL) return;
    int x = (idx / stride) % 96;
    float acc = in[idx] * w[0];
    #pragma unroll
    for (int t = 1; t < 7; ++t) {
        float a = (x - t >= 0) ? in[idx - t * stride] : 0.0f;
        float b = (x + t < 96) ? in[idx + t * stride] : 0.0f;
        acc += (a + b) * w[t];
    }
    outp[idx] = acc * inv;
}
__global__ void k_blur_merge(const float* __restrict__ in, const float* __restrict__ ltm_t,
                             float* __restrict__ oT) {
    float w[7], inv; gw(w, inv);
    int idx = blockIdx.x * blockDim.x + threadIdx.x;
    if (idx >= TVOL) return;
    int x = idx % 96;
    float acc = in[idx] * w[0];
    #pragma unroll
    for (int t = 1; t < 7; ++t) {
        float a = (x - t >= 0) ? in[idx - t] : 0.0f;
        float b = (x + t < 96) ? in[idx + t] : 0.0f;
        acc += (a + b) * w[t];
    }
    float xi = (idx < 96 * 96 * 96) ? 0.005f : 0.003f;
    oT[idx] = ltm_t[idx] + xi * (acc * inv);
}

extern "C" void kernel_launch(void* const* d_in, const int* in_sizes, int n_in,
                              void* d_out, int out_size) {
    (void)in_sizes; (void)n_in; (void)out_size;
    const float* stm_K   = (const float*)d_in[0];
    const float* stm_V   = (const float*)d_in[1];
    const float* stm_e   = (const float*)d_in[2];
    const float* stm_h   = (const float*)d_in[3];
    const float* ltm_K   = (const float*)d_in[4];
    const float* ltm_V   = (const float*)d_in[5];
    const float* ltm_e   = (const float*)d_in[6];
    const float* ltm_h   = (const float*)d_in[7];
    const float* W       = (const float*)d_in[8];
    const float* b       = (const float*)d_in[9];
    const float* stm_t   = (const float*)d_in[10];
    const float* ltm_t   = (const float*)d_in[11];
    const float* fatigue = (const float*)d_in[12];
    const int*   stm_act = (const int*)d_in[13];
    const int*   ltm_act = (const int*)d_in[14];

    float* out = (float*)d_out;
    float* oK  = out;                 // 65536*64
    float* oV  = out + 4194304;       // 65536*128
    float* oe  = out + 12582912;      // 65536*4
    float* oh  = out + 12845056;      // 65536
    float* oSV = out + 12910592;      // 65536*128
    float* oT  = out + 21299200;      // 5*96^3
    float* oF  = out + 25722880;      // 1

    static cudaStream_t sB = 0, sC = 0, sD = 0;
    static cudaEvent_t eR = 0, eB = 0, eC = 0, eD = 0;
    static bool init_done = false;
    if (!init_done) {
        cudaFuncSetAttribute(k_sims, cudaFuncAttributeMaxDynamicSharedMemorySize, SIMS_SMEM);
        cudaStreamCreateWithFlags(&sB, cudaStreamNonBlocking);
        cudaStreamCreateWithFlags(&sC, cudaStreamNonBlocking);
        cudaStreamCreateWithFlags(&sD, cudaStreamNonBlocking);
        cudaEventCreateWithFlags(&eR, cudaEventDisableTiming);
        cudaEventCreateWithFlags(&eB, cudaEventDisableTiming);
        cudaEventCreateWithFlags(&eC, cudaEventDisableTiming);
        cudaEventCreateWithFlags(&eD, cudaEventDisableTiming);
        init_done = true;
    }

    // fork
    cudaEventRecord(eR, 0);
    cudaStreamWaitEvent(sB, eR, 0);
    cudaStreamWaitEvent(sC, eR, 0);
    cudaStreamWaitEvent(sD, eR, 0);

    // side chain B: base copy + free slot list (needed by matched/unmatch)
    k_copy<<<12608, 256, 0, sB>>>((const float4*)ltm_K, (const float4*)ltm_V,
                                  (const float4*)ltm_e, (const float4*)ltm_h,
                                  (float4*)oK);
    k_freeslots<<<1, 1024, 0, sB>>>(ltm_act);
    cudaEventRecord(eB, sB);

    // side chain C: stm_V clip
    k_stmv<<<8192, 256, 0, sC>>>(stm_V, oSV);
    cudaEventRecord(eC, sC);

    // side chain D: terrain blur + merge
    int tb = (TVOL + 255) / 256;
    k_blur<<<tb, 256, 0, sD>>>(stm_t, g_tb0, 96 * 96);
    k_blur<<<tb, 256, 0, sD>>>(g_tb0, g_tb1, 96);
    k_blur_merge<<<tb, 256, 0, sD>>>(g_tb1, ltm_t, oT);
    cudaEventRecord(eD, sD);

    // critical path (legacy stream)
    k_histlkn<<<16384, 256>>>(ltm_K, ltm_act, stm_h, stm_act);
    k_prep<<<1, 1024>>>(fatigue, oF, stm_h, stm_act);
    k_proj<<<2048, 64>>>(stm_K, stm_h, W, b);
    k_sims<<<dim3(32, 9), 256, SIMS_SMEM>>>();

    cudaStreamWaitEvent(0, eB, 0);
    k_matched<<<2048, 64>>>(stm_V, stm_e, stm_h, oK, oV, oe, oh);
    k_rank<<<8, 256>>>();
    k_unmatch<<<2048, 64>>>(stm_V, stm_e, oK, oV, oe, oh);

    // join remaining side chains
    cudaStreamWaitEvent(0, eC, 0);
    cudaStreamWaitEvent(0, eD, 0);
}

// round 7
// speedup vs baseline: 1.9890x; 1.7354x over previous
#include <cuda_runtime.h>
#include <cstdint>
#include <math.h>

#define N_STM 65536
#define N_LTM 65536
#define TOP_M 2048
#define NBIN  4096
#define TVOL  (5*96*96*96)

// scratch (static zero-init; every kernel restores its state for graph replay)
__device__ int                g_hist[NBIN];
__device__ int                g_scal[8];   // 4:n_act 5:n_stages
__device__ int                g_sel[TOP_M];
__device__ int                g_boundary[N_STM];
__device__ float              g_Kproj[TOP_M*64];
__device__ float              g_kpT[64*TOP_M];                 // [k][m]
__device__ float              g_omega[TOP_M];
__device__ float              g_lknC[(size_t)(N_LTM+128)*64];  // compacted active lkn
__device__ unsigned           g_ajinv[N_LTM+128];              // ~orig_j per compacted row
__device__ unsigned long long g_best[TOP_M];
__device__ unsigned long long g_key[TOP_M];
__device__ int                g_unm[TOP_M];
__device__ int                g_rank[TOP_M];
__device__ int                g_free[TOP_M];
__device__ __align__(16) float g_tb0[TVOL];

__device__ __forceinline__ unsigned fmono(float f) {
    unsigned u = __float_as_uint(f);
    return (u & 0x80000000u) ? ~u : (u | 0x80000000u);
}
__device__ __forceinline__ float funmono(unsigned m) {
    unsigned u = (m & 0x80000000u) ? (m ^ 0x80000000u) : ~m;
    return __uint_as_float(u);
}
__device__ __forceinline__ unsigned long long dup2(float x) {
    unsigned long long r; unsigned xi = __float_as_uint(x);
    asm("mov.b64 %0, {%1,%2};" : "=l"(r) : "r"(xi), "r"(xi));
    return r;
}
__device__ __forceinline__ void fma2(unsigned long long& d,
                                     unsigned long long a, unsigned long long b) {
    asm("fma.rn.f32x2 %0, %1, %2, %0;" : "+l"(d) : "l"(a), "l"(b));
}
__device__ __forceinline__ unsigned long long stm_key(int i, float h) {
    return ((unsigned long long)__float_as_uint(h) << 32) | (0xFFFFFFFFu - (unsigned)i);
}
__device__ __forceinline__ int hbin(float h) {
    return min(max((int)(h * (float)NBIN), 0), NBIN - 1);
}
__device__ __forceinline__ void gw(float* w, float& inv) {
    w[0] = 1.0f; float sum = 1.0f;
    #pragma unroll
    for (int i = 1; i < 7; ++i) {
        w[i] = expf(-0.5f * (float)(i * i) / 4.0f);
        sum += 2.0f * w[i];
    }
    inv = 1.0f / sum;
}

// ---- base-state copy: ltm {K,V,e,h} -> contiguous head of d_out -----------
__global__ void k_copy(const float4* __restrict__ K, const float4* __restrict__ V,
                       const float4* __restrict__ e, const float4* __restrict__ h,
                       float4* __restrict__ out) {
    int i = blockIdx.x * blockDim.x + threadIdx.x;   // 3227648 total
    float4 v;
    if (i < 1048576)       v = K[i];
    else if (i < 3145728)  v = V[i - 1048576];
    else if (i < 3211264)  v = e[i - 3145728];
    else                   v = h[i - 3211264];
    out[i] = v;
}

// ---- 1: ltm_K normalize + active compaction  |  stm histogram -------------
__global__ void k_histlkn(const float* __restrict__ ltm_K, const int* __restrict__ ltm_act,
                          const float* __restrict__ stm_h, const int* __restrict__ stm_act) {
    __shared__ float part[8];
    __shared__ int sact[4];
    __shared__ int sbase;
    int tid = threadIdx.x;
    int g = tid >> 6, c = tid & 63, wid = tid >> 5, lane = tid & 31;
    int j = blockIdx.x * 4 + g;
    float v = ltm_K[(size_t)j * 64 + c];
    float sq = v * v;
    #pragma unroll
    for (int off = 16; off; off >>= 1) sq += __shfl_xor_sync(0xFFFFFFFFu, sq, off);
    if (lane == 0) part[wid] = sq;
    int a = (ltm_act[j] > 0) ? 1 : 0;
    if (c == 0) sact[g] = a;
    __syncthreads();
    if (tid == 0) {
        int tot = sact[0] + sact[1] + sact[2] + sact[3];
        sbase = tot ? atomicAdd(&g_scal[4], tot) : 0;
    }
    __syncthreads();
    if (a) {
        int off = 0;
        #pragma unroll
        for (int x = 0; x < 4; ++x) if (x < g) off += sact[x];
        int pos = sbase + off;
        float tot = part[g * 2] + part[g * 2 + 1];
        g_lknC[(size_t)pos * 64 + c] = v / (sqrtf(tot) + 1e-8f);
        if (c == 0) g_ajinv[pos] = 0xFFFFFFFFu - (unsigned)j;
    }
    int i = blockIdx.x * 256 + tid;
    if (i < N_STM && stm_act[i] > 0) atomicAdd(&g_hist[hbin(stm_h[i])], 1);
}

// ---- 2: merged threshold + pad + top-M compaction + tie-break (1 block) ----
__global__ void k_prep(const float* __restrict__ fat, float* __restrict__ oF,
                       const float* __restrict__ h, const int* __restrict__ act) {
    __shared__ int s[1024];
    __shared__ int sT, sCnt, ssel, sbnd;
    int t = threadIdx.x;
    int base = NBIN - 1 - 4 * t;
    int h0 = g_hist[base], h1 = g_hist[base-1], h2 = g_hist[base-2], h3 = g_hist[base-3];
    g_hist[base] = 0; g_hist[base-1] = 0; g_hist[base-2] = 0; g_hist[base-3] = 0;
    int sum = h0 + h1 + h2 + h3;
    s[t] = sum;
    if (t == 0) { ssel = 0; sbnd = 0; }
    __syncthreads();
    for (int off = 1; off < 1024; off <<= 1) {
        int v = s[t], a2 = (t >= off) ? s[t - off] : 0;
        __syncthreads(); s[t] = v + a2; __syncthreads();
    }
    int c = s[t] - sum;
    int hh[4] = {h0, h1, h2, h3};
    #pragma unroll
    for (int q = 0; q < 4; ++q) {
        if (c < TOP_M && c + hh[q] >= TOP_M) { sT = base - q; sCnt = c; }
        c += hh[q];
    }
    int n_act = g_scal[4];
    for (int idx = t; idx < 128 * 64; idx += 1024)
        g_lknC[(size_t)(n_act + (idx >> 6)) * 64 + (idx & 63)] = 0.0f;
    if (t < 128) g_ajinv[n_act + t] = 0u;
    if (t == 0) {
        g_scal[5] = (n_act + 127) >> 7;
        oF[0] = 0.2f * fat[0];
    }
    __syncthreads();
    int T = sT;
    for (int b2 = 0; b2 < N_STM; b2 += 4096) {
        int ia[4]; float ha[4];
        #pragma unroll
        for (int q = 0; q < 4; ++q) {
            int i = b2 + q * 1024 + t;
            ia[q] = act[i]; ha[q] = h[i];
        }
        #pragma unroll
        for (int q = 0; q < 4; ++q) {
            if (ia[q] > 0) {
                int bn = hbin(ha[q]);
                int i = b2 + q * 1024 + t;
                if (bn > T)       g_sel[atomicAdd(&ssel, 1)] = i;
                else if (bn == T) g_boundary[atomicAdd(&sbnd, 1)] = i;
            }
        }
    }
    __syncthreads();
    int B = sbnd, need = TOP_M - sCnt;
    for (int cc = t; cc < B; cc += 1024) {
        int i = g_boundary[cc];
        unsigned long long k = stm_key(i, h[i]);
        int r = 0;
        for (int q = 0; q < B; ++q) {
            int i2 = g_boundary[q];
            r += (stm_key(i2, h[i2]) > k);
        }
        if (r < need) g_sel[atomicAdd(&ssel, 1)] = i;
    }
    __syncthreads();
    if (t == 0) g_scal[4] = 0;   // restore for graph replay
}

// ---- 3: projection + kp normalize (writes transposed kpT) ------------------
__global__ void k_proj(const float* __restrict__ stm_K, const float* __restrict__ stm_h,
                       const float* __restrict__ W, const float* __restrict__ b) {
    int m = blockIdx.x, c = threadIdx.x;
    __shared__ float sK[16];
    __shared__ float ws[2];
    int s = g_sel[m];
    if (c < 16) sK[c] = stm_K[(size_t)s * 16 + c];
    __syncthreads();
    float acc = b[c];
    #pragma unroll
    for (int k = 0; k < 16; ++k) acc = fmaf(sK[k], W[k * 64 + c], acc);
    float sq = acc * acc;
    #pragma unroll
    for (int off = 16; off; off >>= 1) sq += __shfl_xor_sync(0xFFFFFFFFu, sq, off);
    if ((c & 31) == 0) ws[c >> 5] = sq;
    __syncthreads();
    g_Kproj[m * 64 + c] = acc;
    g_kpT[c * TOP_M + m] = acc / (sqrtf(ws[0] + ws[1]) + 1e-8f);
    if (c == 0) g_omega[m] = 0.05f * stm_h[s];
}

// ---- 4: fused sims GEMM + argmax; lk pre-duplicated as f32x2 pairs ---------
// smem: kp_s [64k][64m] floats (16KB), lkd [128j][65] u64 (66560B), jinv 512B.
#define SIMS_SMEM (64*64*4 + 128*65*8 + 128*4)   // 83456 B
__global__ void __launch_bounds__(256, 2) k_sims() {
    extern __shared__ float sm[];
    float* kp_s = sm;                                           // [k][64]
    unsigned long long* lkd = (unsigned long long*)(sm + 4096); // [j][65]
    unsigned* jinv_s = (unsigned*)(sm + 4096 + 128 * 65 * 2);
    const int tid = threadIdx.x;
    const int mb = tid >> 5;
    const int jb = tid & 31;
    const int m0 = blockIdx.x * 64;
    const int ns = g_scal[5];

    for (int idx = tid; idx < 4096; idx += 256) {
        int m = idx & 63, k = idx >> 6;
        kp_s[k * 64 + m] = g_kpT[k * TOP_M + m0 + m];
    }

    unsigned long long run[8];
    #pragma unroll
    for (int i = 0; i < 8; ++i) run[i] = 0ull;

    int s = blockIdx.y;
    float4 pre[8];
    unsigned pj = 0;
    {
        int j0 = s * 128;
        #pragma unroll
        for (int it = 0; it < 8; ++it) {
            int idx = tid + it * 256;
            pre[it] = reinterpret_cast<const float4*>(g_lknC)
                          [(size_t)(j0 + (idx >> 4)) * 16 + (idx & 15)];
        }
        if (tid < 128) pj = g_ajinv[j0 + tid];
    }

    for (; s < ns; ) {
        __syncthreads();
        #pragma unroll
        for (int it = 0; it < 8; ++it) {
            int idx = tid + it * 256;
            unsigned long long* dst = &lkd[(idx >> 4) * 65 + (idx & 15) * 4];
            dst[0] = dup2(pre[it].x); dst[1] = dup2(pre[it].y);
            dst[2] = dup2(pre[it].z); dst[3] = dup2(pre[it].w);
        }
        if (tid < 128) jinv_s[tid] = pj;
        __syncthreads();

        int snext = s + gridDim.y;
        if (snext < ns) {
            int j0 = snext * 128;
            #pragma unroll
            for (int it = 0; it < 8; ++it) {
                int idx = tid + it * 256;
                pre[it] = reinterpret_cast<const float4*>(g_lknC)
                              [(size_t)(j0 + (idx >> 4)) * 16 + (idx & 15)];
            }
            if (tid < 128) pj = g_ajinv[j0 + tid];
        }

        unsigned long long acc[4][4];
        #pragma unroll
        for (int a = 0; a < 4; ++a)
            #pragma unroll
            for (int q = 0; q < 4; ++q) acc[a][q] = 0ull;

        #pragma unroll 8
        for (int k = 0; k < 64; ++k) {
            const ulonglong2* ap =
                reinterpret_cast<const ulonglong2*>(&kp_s[k * 64 + mb * 8]);
            ulonglong2 A0 = ap[0], A1 = ap[1];   // LDS.128 broadcast
            #pragma unroll
            for (int q = 0; q < 4; ++q) {
                unsigned long long b2 = lkd[(jb + q * 32) * 65 + k];  // LDS.64
                fma2(acc[0][q], A0.x, b2);
                fma2(acc[1][q], A0.y, b2);
                fma2(acc[2][q], A1.x, b2);
                fma2(acc[3][q], A1.y, b2);
            }
        }

        #pragma unroll
        for (int mp = 0; mp < 4; ++mp) {
            #pragma unroll
            for (int q = 0; q < 4; ++q) {
                unsigned lo = (unsigned)(acc[mp][q] & 0xFFFFFFFFull);
                unsigned hi = (unsigned)(acc[mp][q] >> 32);
                unsigned jinv = jinv_s[jb + q * 32];
                unsigned long long pl =
                    ((unsigned long long)fmono(__uint_as_float(lo)) << 32) | jinv;
                unsigned long long ph =
                    ((unsigned long long)fmono(__uint_as_float(hi)) << 32) | jinv;
                if (pl > run[2 * mp])     run[2 * mp]     = pl;
                if (ph > run[2 * mp + 1]) run[2 * mp + 1] = ph;
            }
        }
        s = snext;
    }

    #pragma unroll
    for (int i = 0; i < 8; ++i) {
        #pragma unroll
        for (int off = 16; off; off >>= 1) {
            unsigned long long o = __shfl_xor_sync(0xFFFFFFFFu, run[i], off);
            if (o > run[i]) run[i] = o;
        }
        if (jb == 0) atomicMax(&g_best[m0 + mb * 8 + i], run[i]);
    }
}

// ---- 5: stm_V norm clip -----------------------------------------------------
__global__ void k_stmv(const float* __restrict__ stm_V, float* __restrict__ oSV) {
    int w = threadIdx.x >> 5, lane = threadIdx.x & 31;
    size_t row = (size_t)blockIdx.x * 8 + w;
    float4 v = reinterpret_cast<const float4*>(stm_V)[row * 32 + lane];
    float sq = v.x*v.x + v.y*v.y + v.z*v.z + v.w*v.w;
    #pragma unroll
    for (int off = 16; off; off >>= 1) sq += __shfl_xor_sync(0xFFFFFFFFu, sq, off);
    float sc = fminf(1.0f, 2.0f / (sqrtf(sq) + 1e-8f));
    reinterpret_cast<float4*>(oSV)[row * 32 + lane] =
        make_float4(v.x*sc, v.y*sc, v.z*sc, v.w*sc);
}

// ---- 6: first TOP_M inactive slots (coalesced ballot scan, early exit) ------
__global__ void k_freeslots(const int* __restrict__ act) {
    int t = threadIdx.x, w = t >> 5, lane = t & 31;
    __shared__ int wcnt[32];
    int running = 0;
    for (int tile = 0; tile < 64 && running < TOP_M; ++tile) {
        int i = tile * 1024 + t;
        int inact = (act[i] == 0);
        unsigned bal = __ballot_sync(0xFFFFFFFFu, inact);
        if (lane == 0) wcnt[w] = __popc(bal);
        __syncthreads();
        int pre = 0, total = 0;
        #pragma unroll
        for (int x = 0; x < 32; ++x) {
            int cx = wcnt[x];
            if (x < w) pre += cx;
            total += cx;
        }
        int pos = running + pre + __popc(bal & ((1u << lane) - 1));
        if (inact && pos < TOP_M) g_free[pos] = i;
        running += total;
        __syncthreads();
    }
}

// ---- 7: matched scatter-add (+ restore g_best for replay) ------------------
__global__ void k_matched(const float* __restrict__ stm_V, const float* __restrict__ stm_e,
                          const float* __restrict__ stm_h,
                          float* __restrict__ oK, float* __restrict__ oV,
                          float* __restrict__ oe, float* __restrict__ oh) {
    int m = blockIdx.x, c = threadIdx.x;
    __shared__ unsigned long long sp;
    if (c == 0) { sp = g_best[m]; g_best[m] = 0ull; }
    __syncthreads();
    unsigned long long p = sp;
    float sim = funmono((unsigned)(p >> 32));
    int j = (int)(0xFFFFFFFFu - (unsigned)(p & 0xFFFFFFFFull));
    bool matched = (sim >= 0.5f);
    int s = g_sel[m];
    float om = g_omega[m];
    if (c == 0) {
        g_unm[m] = matched ? 0 : 1;
        g_key[m] = stm_key(s, stm_h[s]);
        if (matched) atomicAdd(&oh[j], om);
    }
    if (matched) {
        atomicAdd(&oK[(size_t)j * 64 + c], om * g_Kproj[m * 64 + c]);
        atomicAdd(&oV[(size_t)j * 128 + c], om * stm_V[(size_t)s * 128 + c]);
        atomicAdd(&oV[(size_t)j * 128 + 64 + c], om * stm_V[(size_t)s * 128 + 64 + c]);
        if (c < 4) atomicAdd(&oe[(size_t)j * 4 + c], om * stm_e[(size_t)s * 4 + c]);
    }
}

// ---- 8: rank unmatched (h desc, idx asc) -------------------------------------
__global__ void k_rank() {
    __shared__ unsigned long long sk[TOP_M];
    __shared__ unsigned char su[TOP_M];
    int t = threadIdx.x;
    for (int i = t; i < TOP_M; i += 256) { sk[i] = g_key[i]; su[i] = (unsigned char)g_unm[i]; }
    __syncthreads();
    int m = blockIdx.x * 256 + t;
    if (g_unm[m]) {
        unsigned long long k = sk[m];
        int r = 0;
        for (int i = 0; i < TOP_M; ++i) r += (su[i] && sk[i] > k);
        g_rank[m] = r;
    }
}

// ---- 9: unmatched fresh-slot writes -------------------------------------------
__global__ void k_unmatch(const float* __restrict__ stm_V, const float* __restrict__ stm_e,
                          float* __restrict__ oK, float* __restrict__ oV,
                          float* __restrict__ oe, float* __restrict__ oh) {
    int m = blockIdx.x;
    if (!g_unm[m]) return;
    int slot = g_free[g_rank[m]], c = threadIdx.x, s = g_sel[m];
    oK[(size_t)slot * 64 + c] = g_Kproj[m * 64 + c];
    oV[(size_t)slot * 128 + c] = stm_V[(size_t)s * 128 + c];
    oV[(size_t)slot * 128 + 64 + c] = stm_V[(size_t)s * 128 + 64 + c];
    if (c < 4) oe[(size_t)slot * 4 + c] = stm_e[(size_t)s * 4 + c];
    if (c == 0) oh[slot] = g_omega[m];
}

// ---- blur pass 1: D axis, float4 vectorized ----------------------------------
__global__ void k_blurD(const float4* __restrict__ in, float4* __restrict__ outp) {
    float w[7], inv; gw(w, inv);
    int i = blockIdx.x * blockDim.x + threadIdx.x;   // < TVOL/4
    if (i >= TVOL / 4) return;
    int d = (i / 2304) % 96;
    float4 c = in[i];
    float4 acc = make_float4(c.x * w[0], c.y * w[0], c.z * w[0], c.w * w[0]);
    #pragma unroll
    for (int t = 1; t < 7; ++t) {
        if (d - t >= 0) {
            float4 a = in[i - t * 2304];
            acc.x += a.x * w[t]; acc.y += a.y * w[t];
            acc.z += a.z * w[t]; acc.w += a.w * w[t];
        }
        if (d + t < 96) {
            float4 b = in[i + t * 2304];
            acc.x += b.x * w[t]; acc.y += b.y * w[t];
            acc.z += b.z * w[t]; acc.w += b.w * w[t];
        }
    }
    outp[i] = make_float4(acc.x * inv, acc.y * inv, acc.z * inv, acc.w * inv);
}

// ---- blur passes 2+3 fused: H then W inside one 96x96 smem plane + merge ------
#define BLURHW_SMEM (2 * 9216 * 4)
__global__ void k_blurHW(const float* __restrict__ tb0, const float* __restrict__ ltm_t,
                         float* __restrict__ oT) {
    extern __shared__ float p[];
    float* p0 = p;
    float* p1 = p + 9216;
    float w[7], inv; gw(w, inv);
    int tid = threadIdx.x;
    int plane = blockIdx.x;                 // 0..479 (= c*96 + d)
    size_t base = (size_t)plane * 9216;
    const float4* src = reinterpret_cast<const float4*>(tb0 + base);
    float4* d0 = reinterpret_cast<float4*>(p0);
    for (int i = tid; i < 2304; i += 256) d0[i] = src[i];
    __syncthreads();
    // H blur (stride 96 within plane)
    for (int i = tid; i < 9216; i += 256) {
        int h = i / 96;
        float acc = p0[i] * w[0];
        #pragma unroll
        for (int t = 1; t < 7; ++t) {
            if (h - t >= 0) acc += p0[i - t * 96] * w[t];
            if (h + t < 96) acc += p0[i + t * 96] * w[t];
        }
        p1[i] = acc * inv;
    }
    __syncthreads();
    float xi = (plane < 96) ? 0.005f : 0.003f;
    // W blur (stride 1) + merge
    for (int i = tid; i < 9216; i += 256) {
        int x = i % 96;
        float acc = p1[i] * w[0];
        #pragma unroll
        for (int t = 1; t < 7; ++t) {
            if (x - t >= 0) acc += p1[i - t] * w[t];
            if (x + t < 96) acc += p1[i + t] * w[t];
        }
        oT[base + i] = ltm_t[base + i] + xi * (acc * inv);
    }
}

extern "C" void kernel_launch(void* const* d_in, const int* in_sizes, int n_in,
                              void* d_out, int out_size) {
    (void)in_sizes; (void)n_in; (void)out_size;
    const float* stm_K   = (const float*)d_in[0];
    const float* stm_V   = (const float*)d_in[1];
    const float* stm_e   = (const float*)d_in[2];
    const float* stm_h   = (const float*)d_in[3];
    const float* ltm_K   = (const float*)d_in[4];
    const float* ltm_V   = (const float*)d_in[5];
    const float* ltm_e   = (const float*)d_in[6];
    const float* ltm_h   = (const float*)d_in[7];
    const float* W       = (const float*)d_in[8];
    const float* b       = (const float*)d_in[9];
    const float* stm_t   = (const float*)d_in[10];
    const float* ltm_t   = (const float*)d_in[11];
    const float* fatigue = (const float*)d_in[12];
    const int*   stm_act = (const int*)d_in[13];
    const int*   ltm_act = (const int*)d_in[14];

    float* out = (float*)d_out;
    float* oK  = out;                 // 65536*64
    float* oV  = out + 4194304;       // 65536*128
    float* oe  = out + 12582912;      // 65536*4
    float* oh  = out + 12845056;      // 65536
    float* oSV = out + 12910592;      // 65536*128
    float* oT  = out + 21299200;      // 5*96^3
    float* oF  = out + 25722880;      // 1

    static cudaStream_t sB = 0, sC = 0, sD = 0;
    static cudaEvent_t eR = 0, eB = 0, eC = 0, eD = 0;
    static bool init_done = false;
    if (!init_done) {
        cudaFuncSetAttribute(k_sims, cudaFuncAttributeMaxDynamicSharedMemorySize, SIMS_SMEM);
        cudaFuncSetAttribute(k_blurHW, cudaFuncAttributeMaxDynamicSharedMemorySize, BLURHW_SMEM);
        cudaStreamCreateWithFlags(&sB, cudaStreamNonBlocking);
        cudaStreamCreateWithFlags(&sC, cudaStreamNonBlocking);
        cudaStreamCreateWithFlags(&sD, cudaStreamNonBlocking);
        cudaEventCreateWithFlags(&eR, cudaEventDisableTiming);
        cudaEventCreateWithFlags(&eB, cudaEventDisableTiming);
        cudaEventCreateWithFlags(&eC, cudaEventDisableTiming);
        cudaEventCreateWithFlags(&eD, cudaEventDisableTiming);
        init_done = true;
    }

    // fork
    cudaEventRecord(eR, 0);
    cudaStreamWaitEvent(sB, eR, 0);
    cudaStreamWaitEvent(sC, eR, 0);
    cudaStreamWaitEvent(sD, eR, 0);

    // side chain B: base copy + free slot list
    k_copy<<<12608, 256, 0, sB>>>((const float4*)ltm_K, (const float4*)ltm_V,
                                  (const float4*)ltm_e, (const float4*)ltm_h,
                                  (float4*)oK);
    k_freeslots<<<1, 1024, 0, sB>>>(ltm_act);
    cudaEventRecord(eB, sB);

    // side chain C: stm_V clip
    k_stmv<<<8192, 256, 0, sC>>>(stm_V, oSV);
    cudaEventRecord(eC, sC);

    // side chain D: terrain blur + merge (D pass, then fused H+W+merge)
    k_blurD<<<(TVOL / 4 + 255) / 256, 256, 0, sD>>>((const float4*)stm_t, (float4*)g_tb0);
    k_blurHW<<<480, 256, BLURHW_SMEM, sD>>>(g_tb0, ltm_t, oT);
    cudaEventRecord(eD, sD);

    // critical path (legacy stream)
    k_histlkn<<<16384, 256>>>(ltm_K, ltm_act, stm_h, stm_act);
    k_prep<<<1, 1024>>>(fatigue, oF, stm_h, stm_act);
    k_proj<<<2048, 64>>>(stm_K, stm_h, W, b);
    k_sims<<<dim3(32, 9), 256, SIMS_SMEM>>>();

    cudaStreamWaitEvent(0, eB, 0);
    k_matched<<<2048, 64>>>(stm_V, stm_e, stm_h, oK, oV, oe, oh);
    k_rank<<<8, 256>>>();
    k_unmatch<<<2048, 64>>>(stm_V, stm_e, oK, oV, oe, oh);

    // join remaining side chains
    cudaStreamWaitEvent(0, eC, 0);
    cudaStreamWaitEvent(0, eD, 0);
}

// round 8
// speedup vs baseline: 2.0558x; 1.0336x over previous
#include <cuda_runtime.h>
#include <cstdint>
#include <math.h>

#define N_STM 65536
#define N_LTM 65536
#define TOP_M 2048
#define NBIN  4096
#define TVOL  (5*96*96*96)

// scratch (static zero-init; every kernel restores its state for graph replay)
__device__ int                g_hist[NBIN];
__device__ int                g_scal[8];   // 4:n_act 5:n_stages
__device__ int                g_sel[TOP_M];
__device__ int                g_boundary[N_STM];
__device__ float              g_Kproj[TOP_M*64];
__device__ float              g_kpT[64*TOP_M];                 // [k][m]
__device__ float              g_omega[TOP_M];
__device__ float              g_lknC[(size_t)(N_LTM+128)*64];  // compacted active lkn
__device__ unsigned           g_ajinv[N_LTM+128];              // ~orig_j per compacted row
__device__ unsigned long long g_best[TOP_M];
__device__ unsigned long long g_key[TOP_M];
__device__ int                g_unm[TOP_M];
__device__ int                g_rank[TOP_M];
__device__ int                g_free[TOP_M];

__device__ __forceinline__ unsigned fmono(float f) {
    unsigned u = __float_as_uint(f);
    return (u & 0x80000000u) ? ~u : (u | 0x80000000u);
}
__device__ __forceinline__ float funmono(unsigned m) {
    unsigned u = (m & 0x80000000u) ? (m ^ 0x80000000u) : ~m;
    return __uint_as_float(u);
}
__device__ __forceinline__ unsigned long long dup2(float x) {
    unsigned long long r; unsigned xi = __float_as_uint(x);
    asm("mov.b64 %0, {%1,%2};" : "=l"(r) : "r"(xi), "r"(xi));
    return r;
}
__device__ __forceinline__ void fma2(unsigned long long& d,
                                     unsigned long long a, unsigned long long b) {
    asm("fma.rn.f32x2 %0, %1, %2, %0;" : "+l"(d) : "l"(a), "l"(b));
}
__device__ __forceinline__ unsigned long long stm_key(int i, float h) {
    return ((unsigned long long)__float_as_uint(h) << 32) | (0xFFFFFFFFu - (unsigned)i);
}
__device__ __forceinline__ int hbin(float h) {
    return min(max((int)(h * (float)NBIN), 0), NBIN - 1);
}
__device__ __forceinline__ void gw(float* w, float& inv) {
    w[0] = 1.0f; float sum = 1.0f;
    #pragma unroll
    for (int i = 1; i < 7; ++i) {
        w[i] = expf(-0.5f * (float)(i * i) / 4.0f);
        sum += 2.0f * w[i];
    }
    inv = 1.0f / sum;
}

// ---- base-state copy: ltm {K,V,e,h} -> contiguous head of d_out -----------
__global__ void k_copy(const float4* __restrict__ K, const float4* __restrict__ V,
                       const float4* __restrict__ e, const float4* __restrict__ h,
                       float4* __restrict__ out) {
    int i = blockIdx.x * blockDim.x + threadIdx.x;   // 3227648 total
    float4 v;
    if (i < 1048576)       v = K[i];
    else if (i < 3145728)  v = V[i - 1048576];
    else if (i < 3211264)  v = e[i - 3145728];
    else                   v = h[i - 3211264];
    out[i] = v;
}

// ---- 1: ltm_K normalize + active compaction  |  stm histogram -------------
__global__ void k_histlkn(const float* __restrict__ ltm_K, const int* __restrict__ ltm_act,
                          const float* __restrict__ stm_h, const int* __restrict__ stm_act) {
    __shared__ float part[8];
    __shared__ int sact[4];
    __shared__ int sbase;
    int tid = threadIdx.x;
    int g = tid >> 6, c = tid & 63, wid = tid >> 5, lane = tid & 31;
    int j = blockIdx.x * 4 + g;
    float v = ltm_K[(size_t)j * 64 + c];
    float sq = v * v;
    #pragma unroll
    for (int off = 16; off; off >>= 1) sq += __shfl_xor_sync(0xFFFFFFFFu, sq, off);
    if (lane == 0) part[wid] = sq;
    int a = (ltm_act[j] > 0) ? 1 : 0;
    if (c == 0) sact[g] = a;
    __syncthreads();
    if (tid == 0) {
        int tot = sact[0] + sact[1] + sact[2] + sact[3];
        sbase = tot ? atomicAdd(&g_scal[4], tot) : 0;
    }
    __syncthreads();
    if (a) {
        int off = 0;
        #pragma unroll
        for (int x = 0; x < 4; ++x) if (x < g) off += sact[x];
        int pos = sbase + off;
        float tot = part[g * 2] + part[g * 2 + 1];
        g_lknC[(size_t)pos * 64 + c] = v / (sqrtf(tot) + 1e-8f);
        if (c == 0) g_ajinv[pos] = 0xFFFFFFFFu - (unsigned)j;
    }
    int i = blockIdx.x * 256 + tid;
    if (i < N_STM && stm_act[i] > 0) atomicAdd(&g_hist[hbin(stm_h[i])], 1);
}

// ---- 2: merged threshold + pad + top-M compaction + tie-break (1 block) ----
__global__ void k_prep(const float* __restrict__ fat, float* __restrict__ oF,
                       const float* __restrict__ h, const int* __restrict__ act) {
    __shared__ int s[1024];
    __shared__ int sT, sCnt, ssel, sbnd;
    int t = threadIdx.x;
    int base = NBIN - 1 - 4 * t;
    int h0 = g_hist[base], h1 = g_hist[base-1], h2 = g_hist[base-2], h3 = g_hist[base-3];
    g_hist[base] = 0; g_hist[base-1] = 0; g_hist[base-2] = 0; g_hist[base-3] = 0;
    int sum = h0 + h1 + h2 + h3;
    s[t] = sum;
    if (t == 0) { ssel = 0; sbnd = 0; }
    __syncthreads();
    for (int off = 1; off < 1024; off <<= 1) {
        int v = s[t], a2 = (t >= off) ? s[t - off] : 0;
        __syncthreads(); s[t] = v + a2; __syncthreads();
    }
    int c = s[t] - sum;
    int hh[4] = {h0, h1, h2, h3};
    #pragma unroll
    for (int q = 0; q < 4; ++q) {
        if (c < TOP_M && c + hh[q] >= TOP_M) { sT = base - q; sCnt = c; }
        c += hh[q];
    }
    int n_act = g_scal[4];
    for (int idx = t; idx < 128 * 64; idx += 1024)
        g_lknC[(size_t)(n_act + (idx >> 6)) * 64 + (idx & 63)] = 0.0f;
    if (t < 128) g_ajinv[n_act + t] = 0u;
    if (t == 0) {
        g_scal[5] = (n_act + 127) >> 7;
        oF[0] = 0.2f * fat[0];
    }
    __syncthreads();
    int T = sT;
    for (int b2 = 0; b2 < N_STM; b2 += 4096) {
        int ia[4]; float ha[4];
        #pragma unroll
        for (int q = 0; q < 4; ++q) {
            int i = b2 + q * 1024 + t;
            ia[q] = act[i]; ha[q] = h[i];
        }
        #pragma unroll
        for (int q = 0; q < 4; ++q) {
            if (ia[q] > 0) {
                int bn = hbin(ha[q]);
                int i = b2 + q * 1024 + t;
                if (bn > T)       g_sel[atomicAdd(&ssel, 1)] = i;
                else if (bn == T) g_boundary[atomicAdd(&sbnd, 1)] = i;
            }
        }
    }
    __syncthreads();
    int B = sbnd, need = TOP_M - sCnt;
    for (int cc = t; cc < B; cc += 1024) {
        int i = g_boundary[cc];
        unsigned long long k = stm_key(i, h[i]);
        int r = 0;
        for (int q = 0; q < B; ++q) {
            int i2 = g_boundary[q];
            r += (stm_key(i2, h[i2]) > k);
        }
        if (r < need) g_sel[atomicAdd(&ssel, 1)] = i;
    }
    __syncthreads();
    if (t == 0) g_scal[4] = 0;   // restore for graph replay
}

// ---- 3: projection + kp normalize (writes transposed kpT) ------------------
__global__ void k_proj(const float* __restrict__ stm_K, const float* __restrict__ stm_h,
                       const float* __restrict__ W, const float* __restrict__ b) {
    int m = blockIdx.x, c = threadIdx.x;
    __shared__ float sK[16];
    __shared__ float ws[2];
    int s = g_sel[m];
    if (c < 16) sK[c] = stm_K[(size_t)s * 16 + c];
    __syncthreads();
    float acc = b[c];
    #pragma unroll
    for (int k = 0; k < 16; ++k) acc = fmaf(sK[k], W[k * 64 + c], acc);
    float sq = acc * acc;
    #pragma unroll
    for (int off = 16; off; off >>= 1) sq += __shfl_xor_sync(0xFFFFFFFFu, sq, off);
    if ((c & 31) == 0) ws[c >> 5] = sq;
    __syncthreads();
    g_Kproj[m * 64 + c] = acc;
    g_kpT[c * TOP_M + m] = acc / (sqrtf(ws[0] + ws[1]) + 1e-8f);
    if (c == 0) g_omega[m] = 0.05f * stm_h[s];
}

// ---- 4: fused sims GEMM + argmax; lk pre-duplicated as f32x2 pairs ---------
#define SIMS_SMEM (64*64*4 + 128*65*8 + 128*4)   // 83456 B
__global__ void __launch_bounds__(256, 2) k_sims() {
    extern __shared__ float sm[];
    float* kp_s = sm;                                           // [k][64]
    unsigned long long* lkd = (unsigned long long*)(sm + 4096); // [j][65]
    unsigned* jinv_s = (unsigned*)(sm + 4096 + 128 * 65 * 2);
    const int tid = threadIdx.x;
    const int mb = tid >> 5;
    const int jb = tid & 31;
    const int m0 = blockIdx.x * 64;
    const int ns = g_scal[5];

    for (int idx = tid; idx < 4096; idx += 256) {
        int m = idx & 63, k = idx >> 6;
        kp_s[k * 64 + m] = g_kpT[k * TOP_M + m0 + m];
    }

    unsigned long long run[8];
    #pragma unroll
    for (int i = 0; i < 8; ++i) run[i] = 0ull;

    int s = blockIdx.y;
    float4 pre[8];
    unsigned pj = 0;
    {
        int j0 = s * 128;
        #pragma unroll
        for (int it = 0; it < 8; ++it) {
            int idx = tid + it * 256;
            pre[it] = reinterpret_cast<const float4*>(g_lknC)
                          [(size_t)(j0 + (idx >> 4)) * 16 + (idx & 15)];
        }
        if (tid < 128) pj = g_ajinv[j0 + tid];
    }

    for (; s < ns; ) {
        __syncthreads();
        #pragma unroll
        for (int it = 0; it < 8; ++it) {
            int idx = tid + it * 256;
            unsigned long long* dst = &lkd[(idx >> 4) * 65 + (idx & 15) * 4];
            dst[0] = dup2(pre[it].x); dst[1] = dup2(pre[it].y);
            dst[2] = dup2(pre[it].z); dst[3] = dup2(pre[it].w);
        }
        if (tid < 128) jinv_s[tid] = pj;
        __syncthreads();

        int snext = s + gridDim.y;
        if (snext < ns) {
            int j0 = snext * 128;
            #pragma unroll
            for (int it = 0; it < 8; ++it) {
                int idx = tid + it * 256;
                pre[it] = reinterpret_cast<const float4*>(g_lknC)
                              [(size_t)(j0 + (idx >> 4)) * 16 + (idx & 15)];
            }
            if (tid < 128) pj = g_ajinv[j0 + tid];
        }

        unsigned long long acc[4][4];
        #pragma unroll
        for (int a = 0; a < 4; ++a)
            #pragma unroll
            for (int q = 0; q < 4; ++q) acc[a][q] = 0ull;

        #pragma unroll 8
        for (int k = 0; k < 64; ++k) {
            const ulonglong2* ap =
                reinterpret_cast<const ulonglong2*>(&kp_s[k * 64 + mb * 8]);
            ulonglong2 A0 = ap[0], A1 = ap[1];   // LDS.128 broadcast
            #pragma unroll
            for (int q = 0; q < 4; ++q) {
                unsigned long long b2 = lkd[(jb + q * 32) * 65 + k];  // LDS.64
                fma2(acc[0][q], A0.x, b2);
                fma2(acc[1][q], A0.y, b2);
                fma2(acc[2][q], A1.x, b2);
                fma2(acc[3][q], A1.y, b2);
            }
        }

        #pragma unroll
        for (int mp = 0; mp < 4; ++mp) {
            #pragma unroll
            for (int q = 0; q < 4; ++q) {
                unsigned lo = (unsigned)(acc[mp][q] & 0xFFFFFFFFull);
                unsigned hi = (unsigned)(acc[mp][q] >> 32);
                unsigned jinv = jinv_s[jb + q * 32];
                unsigned long long pl =
                    ((unsigned long long)fmono(__uint_as_float(lo)) << 32) | jinv;
                unsigned long long ph =
                    ((unsigned long long)fmono(__uint_as_float(hi)) << 32) | jinv;
                if (pl > run[2 * mp])     run[2 * mp]     = pl;
                if (ph > run[2 * mp + 1]) run[2 * mp + 1] = ph;
            }
        }
        s = snext;
    }

    #pragma unroll
    for (int i = 0; i < 8; ++i) {
        #pragma unroll
        for (int off = 16; off; off >>= 1) {
            unsigned long long o = __shfl_xor_sync(0xFFFFFFFFu, run[i], off);
            if (o > run[i]) run[i] = o;
        }
        if (jb == 0) atomicMax(&g_best[m0 + mb * 8 + i], run[i]);
    }
}

// ---- 5: stm_V norm clip -----------------------------------------------------
__global__ void k_stmv(const float* __restrict__ stm_V, float* __restrict__ oSV) {
    int w = threadIdx.x >> 5, lane = threadIdx.x & 31;
    size_t row = (size_t)blockIdx.x * 8 + w;
    float4 v = reinterpret_cast<const float4*>(stm_V)[row * 32 + lane];
    float sq = v.x*v.x + v.y*v.y + v.z*v.z + v.w*v.w;
    #pragma unroll
    for (int off = 16; off; off >>= 1) sq += __shfl_xor_sync(0xFFFFFFFFu, sq, off);
    float sc = fminf(1.0f, 2.0f / (sqrtf(sq) + 1e-8f));
    reinterpret_cast<float4*>(oSV)[row * 32 + lane] =
        make_float4(v.x*sc, v.y*sc, v.z*sc, v.w*sc);
}

// ---- 6: first TOP_M inactive slots (coalesced ballot scan, early exit) ------
__global__ void k_freeslots(const int* __restrict__ act) {
    int t = threadIdx.x, w = t >> 5, lane = t & 31;
    __shared__ int wcnt[32];
    int running = 0;
    for (int tile = 0; tile < 64 && running < TOP_M; ++tile) {
        int i = tile * 1024 + t;
        int inact = (act[i] == 0);
        unsigned bal = __ballot_sync(0xFFFFFFFFu, inact);
        if (lane == 0) wcnt[w] = __popc(bal);
        __syncthreads();
        int pre = 0, total = 0;
        #pragma unroll
        for (int x = 0; x < 32; ++x) {
            int cx = wcnt[x];
            if (x < w) pre += cx;
            total += cx;
        }
        int pos = running + pre + __popc(bal & ((1u << lane) - 1));
        if (inact && pos < TOP_M) g_free[pos] = i;
        running += total;
        __syncthreads();
    }
}

// ---- 7: matched scatter-add (+ restore g_best for replay) ------------------
__global__ void k_matched(const float* __restrict__ stm_V, const float* __restrict__ stm_e,
                          const float* __restrict__ stm_h,
                          float* __restrict__ oK, float* __restrict__ oV,
                          float* __restrict__ oe, float* __restrict__ oh) {
    int m = blockIdx.x, c = threadIdx.x;
    __shared__ unsigned long long sp;
    if (c == 0) { sp = g_best[m]; g_best[m] = 0ull; }
    __syncthreads();
    unsigned long long p = sp;
    float sim = funmono((unsigned)(p >> 32));
    int j = (int)(0xFFFFFFFFu - (unsigned)(p & 0xFFFFFFFFull));
    bool matched = (sim >= 0.5f);
    int s = g_sel[m];
    float om = g_omega[m];
    if (c == 0) {
        g_unm[m] = matched ? 0 : 1;
        g_key[m] = stm_key(s, stm_h[s]);
        if (matched) atomicAdd(&oh[j], om);
    }
    if (matched) {
        atomicAdd(&oK[(size_t)j * 64 + c], om * g_Kproj[m * 64 + c]);
        atomicAdd(&oV[(size_t)j * 128 + c], om * stm_V[(size_t)s * 128 + c]);
        atomicAdd(&oV[(size_t)j * 128 + 64 + c], om * stm_V[(size_t)s * 128 + 64 + c]);
        if (c < 4) atomicAdd(&oe[(size_t)j * 4 + c], om * stm_e[(size_t)s * 4 + c]);
    }
}

// ---- 8: rank unmatched (h desc, idx asc) -------------------------------------
__global__ void k_rank() {
    __shared__ unsigned long long sk[TOP_M];
    __shared__ unsigned char su[TOP_M];
    int t = threadIdx.x;
    for (int i = t; i < TOP_M; i += 256) { sk[i] = g_key[i]; su[i] = (unsigned char)g_unm[i]; }
    __syncthreads();
    int m = blockIdx.x * 256 + t;
    if (g_unm[m]) {
        unsigned long long k = sk[m];
        int r = 0;
        for (int i = 0; i < TOP_M; ++i) r += (su[i] && sk[i] > k);
        g_rank[m] = r;
    }
}

// ---- 9: unmatched fresh-slot writes -------------------------------------------
__global__ void k_unmatch(const float* __restrict__ stm_V, const float* __restrict__ stm_e,
                          float* __restrict__ oK, float* __restrict__ oV,
                          float* __restrict__ oe, float* __restrict__ oh) {
    int m = blockIdx.x;
    if (!g_unm[m]) return;
    int slot = g_free[g_rank[m]], c = threadIdx.x, s = g_sel[m];
    oK[(size_t)slot * 64 + c] = g_Kproj[m * 64 + c];
    oV[(size_t)slot * 128 + c] = stm_V[(size_t)s * 128 + c];
    oV[(size_t)slot * 128 + 64 + c] = stm_V[(size_t)s * 128 + 64 + c];
    if (c < 4) oe[(size_t)slot * 4 + c] = stm_e[(size_t)s * 4 + c];
    if (c == 0) oh[slot] = g_omega[m];
}

// ---- fused 3D gaussian blur + merge: one kernel, all axes -------------------
// Block = one output (c,d) plane. D-axis: stream 13 contributing planes into
// register accumulators (coalesced float4, MLP=9/thread, L2-resident volume).
// Then H-blur and W-blur in smem, merge with ltm_terrain, single write.
#define BLUR_SMEM (2 * 9216 * 4)   // 73728 B
__global__ void __launch_bounds__(256) k_blurAll(const float* __restrict__ stm_t,
                                                 const float* __restrict__ ltm_t,
                                                 float* __restrict__ oT) {
    extern __shared__ float p[];
    float* p0 = p;
    float* p1 = p + 9216;
    float w[7], inv; gw(w, inv);
    int tid = threadIdx.x;
    int plane = blockIdx.x;              // c*96 + d
    int c = plane / 96, d = plane % 96;
    size_t cbase = (size_t)c * 96 * 9216;

    float4 acc[9];
    #pragma unroll
    for (int e = 0; e < 9; ++e) acc[e] = make_float4(0.f, 0.f, 0.f, 0.f);

    #pragma unroll
    for (int t = -6; t <= 6; ++t) {
        int dd = d + t;
        if (dd < 0 || dd >= 96) continue;
        float ww = w[t < 0 ? -t : t];
        const float4* src = reinterpret_cast<const float4*>(stm_t + cbase + (size_t)dd * 9216);
        #pragma unroll
        for (int e = 0; e < 9; ++e) {
            float4 v = src[tid + e * 256];
            acc[e].x = fmaf(v.x, ww, acc[e].x);
            acc[e].y = fmaf(v.y, ww, acc[e].y);
            acc[e].z = fmaf(v.z, ww, acc[e].z);
            acc[e].w = fmaf(v.w, ww, acc[e].w);
        }
    }
    float4* d0 = reinterpret_cast<float4*>(p0);
    #pragma unroll
    for (int e = 0; e < 9; ++e) {
        float4 v = acc[e];
        d0[tid + e * 256] = make_float4(v.x * inv, v.y * inv, v.z * inv, v.w * inv);
    }
    __syncthreads();

    // H blur (stride 96; 96t = 0 mod 32 banks -> conflict-free)
    for (int i = tid; i < 9216; i += 256) {
        int h = i / 96;
        float a2 = p0[i] * w[0];
        #pragma unroll
        for (int t = 1; t < 7; ++t) {
            if (h - t >= 0) a2 += p0[i - t * 96] * w[t];
            if (h + t < 96) a2 += p0[i + t * 96] * w[t];
        }
        p1[i] = a2 * inv;
    }
    __syncthreads();

    float xi = (c == 0) ? 0.005f : 0.003f;
    size_t base = cbase + (size_t)d * 9216;
    for (int i = tid; i < 9216; i += 256) {
        int x = i % 96;
        float a2 = p1[i] * w[0];
        #pragma unroll
        for (int t = 1; t < 7; ++t) {
            if (x - t >= 0) a2 += p1[i - t] * w[t];
            if (x + t < 96) a2 += p1[i + t] * w[t];
        }
        oT[base + i] = ltm_t[base + i] + xi * (a2 * inv);
    }
}

extern "C" void kernel_launch(void* const* d_in, const int* in_sizes, int n_in,
                              void* d_out, int out_size) {
    (void)in_sizes; (void)n_in; (void)out_size;
    const float* stm_K   = (const float*)d_in[0];
    const float* stm_V   = (const float*)d_in[1];
    const float* stm_e   = (const float*)d_in[2];
    const float* stm_h   = (const float*)d_in[3];
    const float* ltm_K   = (const float*)d_in[4];
    const float* ltm_V   = (const float*)d_in[5];
    const float* ltm_e   = (const float*)d_in[6];
    const float* ltm_h   = (const float*)d_in[7];
    const float* W       = (const float*)d_in[8];
    const float* b       = (const float*)d_in[9];
    const float* stm_t   = (const float*)d_in[10];
    const float* ltm_t   = (const float*)d_in[11];
    const float* fatigue = (const float*)d_in[12];
    const int*   stm_act = (const int*)d_in[13];
    const int*   ltm_act = (const int*)d_in[14];

    float* out = (float*)d_out;
    float* oK  = out;                 // 65536*64
    float* oV  = out + 4194304;       // 65536*128
    float* oe  = out + 12582912;      // 65536*4
    float* oh  = out + 12845056;      // 65536
    float* oSV = out + 12910592;      // 65536*128
    float* oT  = out + 21299200;      // 5*96^3
    float* oF  = out + 25722880;      // 1

    static cudaStream_t sB = 0, sC = 0, sD = 0;
    static cudaEvent_t eR = 0, eB = 0, eC = 0, eD = 0;
    static bool init_done = false;
    if (!init_done) {
        cudaFuncSetAttribute(k_sims, cudaFuncAttributeMaxDynamicSharedMemorySize, SIMS_SMEM);
        cudaFuncSetAttribute(k_blurAll, cudaFuncAttributeMaxDynamicSharedMemorySize, BLUR_SMEM);
        cudaStreamCreateWithFlags(&sB, cudaStreamNonBlocking);
        cudaStreamCreateWithFlags(&sC, cudaStreamNonBlocking);
        cudaStreamCreateWithFlags(&sD, cudaStreamNonBlocking);
        cudaEventCreateWithFlags(&eR, cudaEventDisableTiming);
        cudaEventCreateWithFlags(&eB, cudaEventDisableTiming);
        cudaEventCreateWithFlags(&eC, cudaEventDisableTiming);
        cudaEventCreateWithFlags(&eD, cudaEventDisableTiming);
        init_done = true;
    }

    // fork
    cudaEventRecord(eR, 0);
    cudaStreamWaitEvent(sB, eR, 0);
    cudaStreamWaitEvent(sC, eR, 0);
    cudaStreamWaitEvent(sD, eR, 0);

    // side chain B: base copy + free slot list
    k_copy<<<12608, 256, 0, sB>>>((const float4*)ltm_K, (const float4*)ltm_V,
                                  (const float4*)ltm_e, (const float4*)ltm_h,
                                  (float4*)oK);
    k_freeslots<<<1, 1024, 0, sB>>>(ltm_act);
    cudaEventRecord(eB, sB);

    // side chain C: stm_V clip
    k_stmv<<<8192, 256, 0, sC>>>(stm_V, oSV);
    cudaEventRecord(eC, sC);

    // side chain D: fused terrain blur + merge
    k_blurAll<<<480, 256, BLUR_SMEM, sD>>>(stm_t, ltm_t, oT);
    cudaEventRecord(eD, sD);

    // critical path (legacy stream)
    k_histlkn<<<16384, 256>>>(ltm_K, ltm_act, stm_h, stm_act);
    k_prep<<<1, 1024>>>(fatigue, oF, stm_h, stm_act);
    k_proj<<<2048, 64>>>(stm_K, stm_h, W, b);
    k_sims<<<dim3(32, 9), 256, SIMS_SMEM>>>();

    cudaStreamWaitEvent(0, eB, 0);
    k_matched<<<2048, 64>>>(stm_V, stm_e, stm_h, oK, oV, oe, oh);
    k_rank<<<8, 256>>>();
    k_unmatch<<<2048, 64>>>(stm_V, stm_e, oK, oV, oe, oh);

    // join remaining side chains
    cudaStreamWaitEvent(0, eC, 0);
    cudaStreamWaitEvent(0, eD, 0);
}

// round 9
// speedup vs baseline: 2.7260x; 1.3260x over previous
#include <cuda_runtime.h>
#include <cstdint>
#include <math.h>

#define N_STM 65536
#define N_LTM 65536
#define TOP_M 2048
#define NBIN  4096
#define TVOL  (5*96*96*96)

// scratch (static zero-init; every kernel restores its state for graph replay)
__device__ int                g_hist[NBIN];
__device__ int                g_scal[8];   // 4:n_act 5:n_stages
__device__ int                g_sel[TOP_M];
__device__ int                g_boundary[N_STM];
__device__ float              g_Kproj[TOP_M*64];
__device__ float              g_kpT[64*TOP_M];                 // [k][m]
__device__ float              g_omega[TOP_M];
__device__ float              g_lknC[(size_t)(N_LTM+128)*64];  // compacted active lkn
__device__ unsigned           g_ajinv[N_LTM+128];              // ~orig_j per compacted row
__device__ unsigned long long g_best[TOP_M];
__device__ unsigned long long g_key[TOP_M];
__device__ int                g_unm[TOP_M];
__device__ int                g_rank[TOP_M];
__device__ int                g_free[TOP_M];

__device__ __forceinline__ unsigned fmono(float f) {
    unsigned u = __float_as_uint(f);
    return (u & 0x80000000u) ? ~u : (u | 0x80000000u);
}
__device__ __forceinline__ float funmono(unsigned m) {
    unsigned u = (m & 0x80000000u) ? (m ^ 0x80000000u) : ~m;
    return __uint_as_float(u);
}
__device__ __forceinline__ unsigned long long dup2(float x) {
    unsigned long long r; unsigned xi = __float_as_uint(x);
    asm("mov.b64 %0, {%1,%2};" : "=l"(r) : "r"(xi), "r"(xi));
    return r;
}
__device__ __forceinline__ void fma2(unsigned long long& d,
                                     unsigned long long a, unsigned long long b) {
    asm("fma.rn.f32x2 %0, %1, %2, %0;" : "+l"(d) : "l"(a), "l"(b));
}
__device__ __forceinline__ unsigned long long stm_key(int i, float h) {
    return ((unsigned long long)__float_as_uint(h) << 32) | (0xFFFFFFFFu - (unsigned)i);
}
__device__ __forceinline__ int hbin(float h) {
    return min(max((int)(h * (float)NBIN), 0), NBIN - 1);
}
__device__ __forceinline__ void gw(float* w, float& inv) {
    w[0] = 1.0f; float sum = 1.0f;
    #pragma unroll
    for (int i = 1; i < 7; ++i) {
        w[i] = expf(-0.5f * (float)(i * i) / 4.0f);
        sum += 2.0f * w[i];
    }
    inv = 1.0f / sum;
}

// ---- base-state copy: ltm {K,V,e,h} -> contiguous head of d_out -----------
__global__ void k_copy(const float4* __restrict__ K, const float4* __restrict__ V,
                       const float4* __restrict__ e, const float4* __restrict__ h,
                       float4* __restrict__ out) {
    int i = blockIdx.x * blockDim.x + threadIdx.x;   // 3227648 total
    float4 v;
    if (i < 1048576)       v = K[i];
    else if (i < 3145728)  v = V[i - 1048576];
    else if (i < 3211264)  v = e[i - 3145728];
    else                   v = h[i - 3211264];
    out[i] = v;
}

// ---- 1: ltm_K normalize + active compaction  |  stm histogram -------------
__global__ void k_histlkn(const float* __restrict__ ltm_K, const int* __restrict__ ltm_act,
                          const float* __restrict__ stm_h, const int* __restrict__ stm_act) {
    __shared__ float part[8];
    __shared__ int sact[4];
    __shared__ int sbase;
    int tid = threadIdx.x;
    int g = tid >> 6, c = tid & 63, wid = tid >> 5, lane = tid & 31;
    int j = blockIdx.x * 4 + g;
    float v = ltm_K[(size_t)j * 64 + c];
    float sq = v * v;
    #pragma unroll
    for (int off = 16; off; off >>= 1) sq += __shfl_xor_sync(0xFFFFFFFFu, sq, off);
    if (lane == 0) part[wid] = sq;
    int a = (ltm_act[j] > 0) ? 1 : 0;
    if (c == 0) sact[g] = a;
    __syncthreads();
    if (tid == 0) {
        int tot = sact[0] + sact[1] + sact[2] + sact[3];
        sbase = tot ? atomicAdd(&g_scal[4], tot) : 0;
    }
    __syncthreads();
    if (a) {
        int off = 0;
        #pragma unroll
        for (int x = 0; x < 4; ++x) if (x < g) off += sact[x];
        int pos = sbase + off;
        float tot = part[g * 2] + part[g * 2 + 1];
        g_lknC[(size_t)pos * 64 + c] = v / (sqrtf(tot) + 1e-8f);
        if (c == 0) g_ajinv[pos] = 0xFFFFFFFFu - (unsigned)j;
    }
    int i = blockIdx.x * 256 + tid;
    if (i < N_STM && stm_act[i] > 0) atomicAdd(&g_hist[hbin(stm_h[i])], 1);
}

// ---- 2: merged threshold + pad + top-M compaction + tie-break (1 block) ----
__global__ void k_prep(const float* __restrict__ fat, float* __restrict__ oF,
                       const float* __restrict__ h, const int* __restrict__ act) {
    __shared__ int s[1024];
    __shared__ int sT, sCnt, ssel, sbnd;
    int t = threadIdx.x;
    int base = NBIN - 1 - 4 * t;
    int h0 = g_hist[base], h1 = g_hist[base-1], h2 = g_hist[base-2], h3 = g_hist[base-3];
    g_hist[base] = 0; g_hist[base-1] = 0; g_hist[base-2] = 0; g_hist[base-3] = 0;
    int sum = h0 + h1 + h2 + h3;
    s[t] = sum;
    if (t == 0) { ssel = 0; sbnd = 0; }
    __syncthreads();
    for (int off = 1; off < 1024; off <<= 1) {
        int v = s[t], a2 = (t >= off) ? s[t - off] : 0;
        __syncthreads(); s[t] = v + a2; __syncthreads();
    }
    int c = s[t] - sum;
    int hh[4] = {h0, h1, h2, h3};
    #pragma unroll
    for (int q = 0; q < 4; ++q) {
        if (c < TOP_M && c + hh[q] >= TOP_M) { sT = base - q; sCnt = c; }
        c += hh[q];
    }
    int n_act = g_scal[4];
    for (int idx = t; idx < 128 * 64; idx += 1024)
        g_lknC[(size_t)(n_act + (idx >> 6)) * 64 + (idx & 63)] = 0.0f;
    if (t < 128) g_ajinv[n_act + t] = 0u;
    if (t == 0) {
        g_scal[5] = (n_act + 127) >> 7;
        oF[0] = 0.2f * fat[0];
    }
    __syncthreads();
    int T = sT;
    for (int b2 = 0; b2 < N_STM; b2 += 4096) {
        int ia[4]; float ha[4];
        #pragma unroll
        for (int q = 0; q < 4; ++q) {
            int i = b2 + q * 1024 + t;
            ia[q] = act[i]; ha[q] = h[i];
        }
        #pragma unroll
        for (int q = 0; q < 4; ++q) {
            if (ia[q] > 0) {
                int bn = hbin(ha[q]);
                int i = b2 + q * 1024 + t;
                if (bn > T)       g_sel[atomicAdd(&ssel, 1)] = i;
                else if (bn == T) g_boundary[atomicAdd(&sbnd, 1)] = i;
            }
        }
    }
    __syncthreads();
    int B = sbnd, need = TOP_M - sCnt;
    for (int cc = t; cc < B; cc += 1024) {
        int i = g_boundary[cc];
        unsigned long long k = stm_key(i, h[i]);
        int r = 0;
        for (int q = 0; q < B; ++q) {
            int i2 = g_boundary[q];
            r += (stm_key(i2, h[i2]) > k);
        }
        if (r < need) g_sel[atomicAdd(&ssel, 1)] = i;
    }
    __syncthreads();
    if (t == 0) g_scal[4] = 0;   // restore for graph replay
}

// ---- 3: projection + kp normalize (writes transposed kpT) ------------------
__global__ void k_proj(const float* __restrict__ stm_K, const float* __restrict__ stm_h,
                       const float* __restrict__ W, const float* __restrict__ b) {
    int m = blockIdx.x, c = threadIdx.x;
    __shared__ float sK[16];
    __shared__ float ws[2];
    int s = g_sel[m];
    if (c < 16) sK[c] = stm_K[(size_t)s * 16 + c];
    __syncthreads();
    float acc = b[c];
    #pragma unroll
    for (int k = 0; k < 16; ++k) acc = fmaf(sK[k], W[k * 64 + c], acc);
    float sq = acc * acc;
    #pragma unroll
    for (int off = 16; off; off >>= 1) sq += __shfl_xor_sync(0xFFFFFFFFu, sq, off);
    if ((c & 31) == 0) ws[c >> 5] = sq;
    __syncthreads();
    g_Kproj[m * 64 + c] = acc;
    g_kpT[c * TOP_M + m] = acc / (sqrtf(ws[0] + ws[1]) + 1e-8f);
    if (c == 0) g_omega[m] = 0.05f * stm_h[s];
}

// ---- 4: fused sims GEMM + argmax; lk pre-duplicated as f32x2 pairs ---------
#define SIMS_SMEM (64*64*4 + 128*65*8 + 128*4)   // 83456 B
__global__ void __launch_bounds__(256, 2) k_sims() {
    extern __shared__ float sm[];
    float* kp_s = sm;                                           // [k][64]
    unsigned long long* lkd = (unsigned long long*)(sm + 4096); // [j][65]
    unsigned* jinv_s = (unsigned*)(sm + 4096 + 128 * 65 * 2);
    const int tid = threadIdx.x;
    const int mb = tid >> 5;
    const int jb = tid & 31;
    const int m0 = blockIdx.x * 64;
    const int ns = g_scal[5];

    for (int idx = tid; idx < 4096; idx += 256) {
        int m = idx & 63, k = idx >> 6;
        kp_s[k * 64 + m] = g_kpT[k * TOP_M + m0 + m];
    }

    unsigned long long run[8];
    #pragma unroll
    for (int i = 0; i < 8; ++i) run[i] = 0ull;

    int s = blockIdx.y;
    float4 pre[8];
    unsigned pj = 0;
    {
        int j0 = s * 128;
        #pragma unroll
        for (int it = 0; it < 8; ++it) {
            int idx = tid + it * 256;
            pre[it] = reinterpret_cast<const float4*>(g_lknC)
                          [(size_t)(j0 + (idx >> 4)) * 16 + (idx & 15)];
        }
        if (tid < 128) pj = g_ajinv[j0 + tid];
    }

    for (; s < ns; ) {
        __syncthreads();
        #pragma unroll
        for (int it = 0; it < 8; ++it) {
            int idx = tid + it * 256;
            unsigned long long* dst = &lkd[(idx >> 4) * 65 + (idx & 15) * 4];
            dst[0] = dup2(pre[it].x); dst[1] = dup2(pre[it].y);
            dst[2] = dup2(pre[it].z); dst[3] = dup2(pre[it].w);
        }
        if (tid < 128) jinv_s[tid] = pj;
        __syncthreads();

        int snext = s + gridDim.y;
        if (snext < ns) {
            int j0 = snext * 128;
            #pragma unroll
            for (int it = 0; it < 8; ++it) {
                int idx = tid + it * 256;
                pre[it] = reinterpret_cast<const float4*>(g_lknC)
                              [(size_t)(j0 + (idx >> 4)) * 16 + (idx & 15)];
            }
            if (tid < 128) pj = g_ajinv[j0 + tid];
        }

        unsigned long long acc[4][4];
        #pragma unroll
        for (int a = 0; a < 4; ++a)
            #pragma unroll
            for (int q = 0; q < 4; ++q) acc[a][q] = 0ull;

        #pragma unroll 8
        for (int k = 0; k < 64; ++k) {
            const ulonglong2* ap =
                reinterpret_cast<const ulonglong2*>(&kp_s[k * 64 + mb * 8]);
            ulonglong2 A0 = ap[0], A1 = ap[1];   // LDS.128 broadcast
            #pragma unroll
            for (int q = 0; q < 4; ++q) {
                unsigned long long b2 = lkd[(jb + q * 32) * 65 + k];  // LDS.64
                fma2(acc[0][q], A0.x, b2);
                fma2(acc[1][q], A0.y, b2);
                fma2(acc[2][q], A1.x, b2);
                fma2(acc[3][q], A1.y, b2);
            }
        }

        #pragma unroll
        for (int mp = 0; mp < 4; ++mp) {
            #pragma unroll
            for (int q = 0; q < 4; ++q) {
                unsigned lo = (unsigned)(acc[mp][q] & 0xFFFFFFFFull);
                unsigned hi = (unsigned)(acc[mp][q] >> 32);
                unsigned jinv = jinv_s[jb + q * 32];
                unsigned long long pl =
                    ((unsigned long long)fmono(__uint_as_float(lo)) << 32) | jinv;
                unsigned long long ph =
                    ((unsigned long long)fmono(__uint_as_float(hi)) << 32) | jinv;
                if (pl > run[2 * mp])     run[2 * mp]     = pl;
                if (ph > run[2 * mp + 1]) run[2 * mp + 1] = ph;
            }
        }
        s = snext;
    }

    #pragma unroll
    for (int i = 0; i < 8; ++i) {
        #pragma unroll
        for (int off = 16; off; off >>= 1) {
            unsigned long long o = __shfl_xor_sync(0xFFFFFFFFu, run[i], off);
            if (o > run[i]) run[i] = o;
        }
        if (jb == 0) atomicMax(&g_best[m0 + mb * 8 + i], run[i]);
    }
}

// ---- 5: stm_V norm clip -----------------------------------------------------
__global__ void k_stmv(const float* __restrict__ stm_V, float* __restrict__ oSV) {
    int w = threadIdx.x >> 5, lane = threadIdx.x & 31;
    size_t row = (size_t)blockIdx.x * 8 + w;
    float4 v = reinterpret_cast<const float4*>(stm_V)[row * 32 + lane];
    float sq = v.x*v.x + v.y*v.y + v.z*v.z + v.w*v.w;
    #pragma unroll
    for (int off = 16; off; off >>= 1) sq += __shfl_xor_sync(0xFFFFFFFFu, sq, off);
    float sc = fminf(1.0f, 2.0f / (sqrtf(sq) + 1e-8f));
    reinterpret_cast<float4*>(oSV)[row * 32 + lane] =
        make_float4(v.x*sc, v.y*sc, v.z*sc, v.w*sc);
}

// ---- 6: first TOP_M inactive slots (coalesced ballot scan, early exit) ------
__global__ void k_freeslots(const int* __restrict__ act) {
    int t = threadIdx.x, w = t >> 5, lane = t & 31;
    __shared__ int wcnt[32];
    int running = 0;
    for (int tile = 0; tile < 64 && running < TOP_M; ++tile) {
        int i = tile * 1024 + t;
        int inact = (act[i] == 0);
        unsigned bal = __ballot_sync(0xFFFFFFFFu, inact);
        if (lane == 0) wcnt[w] = __popc(bal);
        __syncthreads();
        int pre = 0, total = 0;
        #pragma unroll
        for (int x = 0; x < 32; ++x) {
            int cx = wcnt[x];
            if (x < w) pre += cx;
            total += cx;
        }
        int pos = running + pre + __popc(bal & ((1u << lane) - 1));
        if (inact && pos < TOP_M) g_free[pos] = i;
        running += total;
        __syncthreads();
    }
}

// ---- 7: matched scatter-add (+ restore g_best for replay) ------------------
__global__ void k_matched(const float* __restrict__ stm_V, const float* __restrict__ stm_e,
                          const float* __restrict__ stm_h,
                          float* __restrict__ oK, float* __restrict__ oV,
                          float* __restrict__ oe, float* __restrict__ oh) {
    int m = blockIdx.x, c = threadIdx.x;
    __shared__ unsigned long long sp;
    if (c == 0) { sp = g_best[m]; g_best[m] = 0ull; }
    __syncthreads();
    unsigned long long p = sp;
    float sim = funmono((unsigned)(p >> 32));
    int j = (int)(0xFFFFFFFFu - (unsigned)(p & 0xFFFFFFFFull));
    bool matched = (sim >= 0.5f);
    int s = g_sel[m];
    float om = g_omega[m];
    if (c == 0) {
        g_unm[m] = matched ? 0 : 1;
        g_key[m] = stm_key(s, stm_h[s]);
        if (matched) atomicAdd(&oh[j], om);
    }
    if (matched) {
        atomicAdd(&oK[(size_t)j * 64 + c], om * g_Kproj[m * 64 + c]);
        atomicAdd(&oV[(size_t)j * 128 + c], om * stm_V[(size_t)s * 128 + c]);
        atomicAdd(&oV[(size_t)j * 128 + 64 + c], om * stm_V[(size_t)s * 128 + 64 + c]);
        if (c < 4) atomicAdd(&oe[(size_t)j * 4 + c], om * stm_e[(size_t)s * 4 + c]);
    }
}

// ---- 8: rank unmatched (h desc, idx asc) -------------------------------------
__global__ void k_rank() {
    __shared__ unsigned long long sk[TOP_M];
    __shared__ unsigned char su[TOP_M];
    int t = threadIdx.x;
    for (int i = t; i < TOP_M; i += 256) { sk[i] = g_key[i]; su[i] = (unsigned char)g_unm[i]; }
    __syncthreads();
    int m = blockIdx.x * 256 + t;
    if (g_unm[m]) {
        unsigned long long k = sk[m];
        int r = 0;
        for (int i = 0; i < TOP_M; ++i) r += (su[i] && sk[i] > k);
        g_rank[m] = r;
    }
}

// ---- 9: unmatched fresh-slot writes -------------------------------------------
__global__ void k_unmatch(const float* __restrict__ stm_V, const float* __restrict__ stm_e,
                          float* __restrict__ oK, float* __restrict__ oV,
                          float* __restrict__ oe, float* __restrict__ oh) {
    int m = blockIdx.x;
    if (!g_unm[m]) return;
    int slot = g_free[g_rank[m]], c = threadIdx.x, s = g_sel[m];
    oK[(size_t)slot * 64 + c] = g_Kproj[m * 64 + c];
    oV[(size_t)slot * 128 + c] = stm_V[(size_t)s * 128 + c];
    oV[(size_t)slot * 128 + 64 + c] = stm_V[(size_t)s * 128 + 64 + c];
    if (c < 4) oe[(size_t)slot * 4 + c] = stm_e[(size_t)s * 4 + c];
    if (c == 0) oh[slot] = g_omega[m];
}

// ---- fused 3D gaussian blur + merge: one kernel, branchless + div-free ------
// p0: H-padded plane, rows h in [-6,101]: 108*96 = 10368 floats.
// p1: W-padded plane, 96 rows * stride 108, data at [h*108 + 6 + x].
#define BLUR_SMEM ((10368 + 10368) * 4)   // 82944 B
__global__ void __launch_bounds__(256) k_blurAll(const float* __restrict__ stm_t,
                                                 const float* __restrict__ ltm_t,
                                                 float* __restrict__ oT) {
    extern __shared__ float p[];
    float* p0 = p;              // padded H plane
    float* p0c = p + 576;       // center (h=0 row)
    float* p1 = p + 10368;      // padded W plane
    float w[7], inv; gw(w, inv);
    int tid = threadIdx.x;
    int plane = blockIdx.x;              // c*96 + d
    int c = plane / 96, d = plane % 96;
    size_t cbase = (size_t)c * 96 * 9216;

    // zero pads
    for (int i = tid; i < 576; i += 256) { p0[i] = 0.0f; p0[9792 + i] = 0.0f; }
    for (int i = tid; i < 1152; i += 256) {
        int row = i / 12, cc = i - row * 12;
        p1[row * 108 + (cc < 6 ? cc : 96 + cc)] = 0.0f;
    }

    // D-axis blur: stream 13 planes, accumulate in registers
    float4 acc[9];
    #pragma unroll
    for (int e = 0; e < 9; ++e) acc[e] = make_float4(0.f, 0.f, 0.f, 0.f);
    #pragma unroll
    for (int t = -6; t <= 6; ++t) {
        int dd = d + t;
        if (dd < 0 || dd >= 96) continue;
        float ww = w[t < 0 ? -t : t];
        const float4* src = reinterpret_cast<const float4*>(stm_t + cbase + (size_t)dd * 9216);
        #pragma unroll
        for (int e = 0; e < 9; ++e) {
            float4 v = src[tid + e * 256];
            acc[e].x = fmaf(v.x, ww, acc[e].x);
            acc[e].y = fmaf(v.y, ww, acc[e].y);
            acc[e].z = fmaf(v.z, ww, acc[e].z);
            acc[e].w = fmaf(v.w, ww, acc[e].w);
        }
    }
    float4* d0 = reinterpret_cast<float4*>(p0c);
    #pragma unroll
    for (int e = 0; e < 9; ++e) {
        float4 v = acc[e];
        d0[tid + e * 256] = make_float4(v.x * inv, v.y * inv, v.z * inv, v.w * inv);
    }
    __syncthreads();

    // H blur: branchless (padded rows), div-free index bookkeeping
    {
        int h = tid / 96;                 // 0..2
        int x = tid - h * 96;
        for (int i = tid; i < 9216; i += 256) {
            float a2 = p0c[i] * w[0];
            #pragma unroll
            for (int t = 1; t < 7; ++t)
                a2 += (p0c[i - t * 96] + p0c[i + t * 96]) * w[t];
            p1[h * 108 + 6 + x] = a2 * inv;
            x += 64; h += 2;
            if (x >= 96) { x -= 96; h += 1; }
        }
    }
    __syncthreads();

    // W blur (branchless via row pads) + merge, div-free
    {
        float xi = (c == 0) ? 0.005f : 0.003f;
        size_t base = cbase + (size_t)d * 9216;
        int h = tid / 96;
        int x = tid - h * 96;
        for (int i = tid; i < 9216; i += 256) {
            const float* row = p1 + h * 108 + 6 + x;
            float a2 = row[0] * w[0];
            #pragma unroll
            for (int t = 1; t < 7; ++t)
                a2 += (row[-t] + row[t]) * w[t];
            oT[base + i] = ltm_t[base + i] + xi * (a2 * inv);
            x += 64; h += 2;
            if (x >= 96) { x -= 96; h += 1; }
        }
    }
}

extern "C" void kernel_launch(void* const* d_in, const int* in_sizes, int n_in,
                              void* d_out, int out_size) {
    (void)in_sizes; (void)n_in; (void)out_size;
    const float* stm_K   = (const float*)d_in[0];
    const float* stm_V   = (const float*)d_in[1];
    const float* stm_e   = (const float*)d_in[2];
    const float* stm_h   = (const float*)d_in[3];
    const float* ltm_K   = (const float*)d_in[4];
    const float* ltm_V   = (const float*)d_in[5];
    const float* ltm_e   = (const float*)d_in[6];
    const float* ltm_h   = (const float*)d_in[7];
    const float* W       = (const float*)d_in[8];
    const float* b       = (const float*)d_in[9];
    const float* stm_t   = (const float*)d_in[10];
    const float* ltm_t   = (const float*)d_in[11];
    const float* fatigue = (const float*)d_in[12];
    const int*   stm_act = (const int*)d_in[13];
    const int*   ltm_act = (const int*)d_in[14];

    float* out = (float*)d_out;
    float* oK  = out;                 // 65536*64
    float* oV  = out + 4194304;       // 65536*128
    float* oe  = out + 12582912;      // 65536*4
    float* oh  = out + 12845056;      // 65536
    float* oSV = out + 12910592;      // 65536*128
    float* oT  = out + 21299200;      // 5*96^3
    float* oF  = out + 25722880;      // 1

    static cudaStream_t sB = 0, sC = 0, sD = 0;
    static cudaEvent_t eR = 0, eB = 0, eC = 0, eD = 0;
    static bool init_done = false;
    if (!init_done) {
        cudaFuncSetAttribute(k_sims, cudaFuncAttributeMaxDynamicSharedMemorySize, SIMS_SMEM);
        cudaFuncSetAttribute(k_blurAll, cudaFuncAttributeMaxDynamicSharedMemorySize, BLUR_SMEM);
        cudaStreamCreateWithFlags(&sB, cudaStreamNonBlocking);
        cudaStreamCreateWithFlags(&sC, cudaStreamNonBlocking);
        cudaStreamCreateWithFlags(&sD, cudaStreamNonBlocking);
        cudaEventCreateWithFlags(&eR, cudaEventDisableTiming);
        cudaEventCreateWithFlags(&eB, cudaEventDisableTiming);
        cudaEventCreateWithFlags(&eC, cudaEventDisableTiming);
        cudaEventCreateWithFlags(&eD, cudaEventDisableTiming);
        init_done = true;
    }

    // fork
    cudaEventRecord(eR, 0);
    cudaStreamWaitEvent(sB, eR, 0);
    cudaStreamWaitEvent(sC, eR, 0);
    cudaStreamWaitEvent(sD, eR, 0);

    // critical path enqueued FIRST (k_sims = 4th launch -> ncu sample target)
    k_histlkn<<<16384, 256>>>(ltm_K, ltm_act, stm_h, stm_act);
    k_prep<<<1, 1024>>>(fatigue, oF, stm_h, stm_act);
    k_proj<<<2048, 64>>>(stm_K, stm_h, W, b);
    k_sims<<<dim3(32, 9), 256, SIMS_SMEM>>>();

    // side chain B: base copy + free slot list
    k_copy<<<12608, 256, 0, sB>>>((const float4*)ltm_K, (const float4*)ltm_V,
                                  (const float4*)ltm_e, (const float4*)ltm_h,
                                  (float4*)oK);
    k_freeslots<<<1, 1024, 0, sB>>>(ltm_act);
    cudaEventRecord(eB, sB);

    // side chain C: stm_V clip
    k_stmv<<<8192, 256, 0, sC>>>(stm_V, oSV);
    cudaEventRecord(eC, sC);

    // side chain D: fused terrain blur + merge
    k_blurAll<<<480, 256, BLUR_SMEM, sD>>>(stm_t, ltm_t, oT);
    cudaEventRecord(eD, sD);

    // tail of critical path
    cudaStreamWaitEvent(0, eB, 0);
    k_matched<<<2048, 64>>>(stm_V, stm_e, stm_h, oK, oV, oe, oh);
    k_rank<<<8, 256>>>();
    k_unmatch<<<2048, 64>>>(stm_V, stm_e, oK, oV, oe, oh);

    // join remaining side chains
    cudaStreamWaitEvent(0, eC, 0);
    cudaStreamWaitEvent(0, eD, 0);
}

// round 11
// speedup vs baseline: 3.7314x; 1.3688x over previous
#include <cuda_runtime.h>
#include <cuda_bf16.h>
#include <cstdint>
#include <math.h>

#define N_STM 65536
#define N_LTM 65536
#define TOP_M 2048
#define NBIN  4096
#define TVOL  (5*96*96*96)
#define NSMAX 516

// ---------------- scratch (static zero-init; replay-safe) -------------------
__device__ int                g_hist[NBIN];
__device__ int                g_scal[8];   // 4:n_act 5:n_stages
__device__ int                g_sel[TOP_M];
__device__ int                g_boundary[N_STM];
__device__ float              g_Kproj[TOP_M*64];
__device__ float              g_kpN[TOP_M*64];
__device__ __align__(16) __nv_bfloat16 g_kpB[TOP_M*64];
__device__ float              g_omega[TOP_M];
__device__ float              g_lknC[(size_t)(N_LTM+128)*64];
__device__ __align__(16) __nv_bfloat16 g_lknB[(size_t)(N_LTM+128)*64];
__device__ unsigned           g_ajinv[N_LTM+128];
__device__ float              g_smax[(size_t)TOP_M*NSMAX];
__device__ unsigned           g_gmaxU[TOP_M];
__device__ unsigned long long g_best[TOP_M];
__device__ unsigned long long g_key[TOP_M];
__device__ int                g_unm[TOP_M];
__device__ int                g_rank[TOP_M];
__device__ int                g_free[TOP_M];

// ---------------- helpers ---------------------------------------------------
__device__ __forceinline__ unsigned fmono(float f) {
    unsigned u = __float_as_uint(f);
    return (u & 0x80000000u) ? ~u : (u | 0x80000000u);
}
__device__ __forceinline__ float funmono(unsigned m) {
    unsigned u = (m & 0x80000000u) ? (m ^ 0x80000000u) : ~m;
    return __uint_as_float(u);
}
__device__ __forceinline__ unsigned long long stm_key(int i, float h) {
    return ((unsigned long long)__float_as_uint(h) << 32) | (0xFFFFFFFFu - (unsigned)i);
}
__device__ __forceinline__ int hbin(float h) {
    return min(max((int)(h * (float)NBIN), 0), NBIN - 1);
}
__device__ __forceinline__ void gw(float* w, float& inv) {
    w[0] = 1.0f; float sum = 1.0f;
    #pragma unroll
    for (int i = 1; i < 7; ++i) {
        w[i] = expf(-0.5f * (float)(i * i) / 4.0f);
        sum += 2.0f * w[i];
    }
    inv = 1.0f / sum;
}
// bf16 m16n8k16 HMMA (standard PTX, sm_80+; no arch-specific suffix)
__device__ __forceinline__ void mma16816(float* c, const unsigned* a, const unsigned* b) {
    asm volatile("mma.sync.aligned.m16n8k16.row.col.f32.bf16.bf16.f32 "
                 "{%0,%1,%2,%3}, {%4,%5,%6,%7}, {%8,%9}, {%0,%1,%2,%3};"
                 : "+f"(c[0]), "+f"(c[1]), "+f"(c[2]), "+f"(c[3])
                 : "r"(a[0]), "r"(a[1]), "r"(a[2]), "r"(a[3]), "r"(b[0]), "r"(b[1]));
}

// ---- base-state copy: ltm {K,V,e,h} -> contiguous head of d_out ------------
__global__ void k_copy(const float4* __restrict__ K, const float4* __restrict__ V,
                       const float4* __restrict__ e, const float4* __restrict__ h,
                       float4* __restrict__ out) {
    int i = blockIdx.x * blockDim.x + threadIdx.x;   // 3227648 total
    float4 v;
    if (i < 1048576)       v = K[i];
    else if (i < 3145728)  v = V[i - 1048576];
    else if (i < 3211264)  v = e[i - 3145728];
    else                   v = h[i - 3211264];
    out[i] = v;
}

// ---- 1: ltm_K normalize + active compaction (fp32 + bf16) | stm histogram --
__global__ void k_histlkn(const float* __restrict__ ltm_K, const int* __restrict__ ltm_act,
                          const float* __restrict__ stm_h, const int* __restrict__ stm_act) {
    __shared__ float part[8];
    __shared__ int sact[4];
    __shared__ int sbase;
    int tid = threadIdx.x;
    int g = tid >> 6, c = tid & 63, wid = tid >> 5, lane = tid & 31;
    int j = blockIdx.x * 4 + g;
    float v = ltm_K[(size_t)j * 64 + c];
    float sq = v * v;
    #pragma unroll
    for (int off = 16; off; off >>= 1) sq += __shfl_xor_sync(0xFFFFFFFFu, sq, off);
    if (lane == 0) part[wid] = sq;
    int a = (ltm_act[j] > 0) ? 1 : 0;
    if (c == 0) sact[g] = a;
    __syncthreads();
    if (tid == 0) {
        int tot = sact[0] + sact[1] + sact[2] + sact[3];
        sbase = tot ? atomicAdd(&g_scal[4], tot) : 0;
    }
    __syncthreads();
    if (a) {
        int off = 0;
        #pragma unroll
        for (int x = 0; x < 4; ++x) if (x < g) off += sact[x];
        int pos = sbase + off;
        float tot = part[g * 2] + part[g * 2 + 1];
        float nv = v / (sqrtf(tot) + 1e-8f);
        g_lknC[(size_t)pos * 64 + c] = nv;
        g_lknB[(size_t)pos * 64 + c] = __float2bfloat16(nv);
        if (c == 0) g_ajinv[pos] = 0xFFFFFFFFu - (unsigned)j;
    }
    int i = blockIdx.x * 256 + tid;
    if (i < N_STM && stm_act[i] > 0) atomicAdd(&g_hist[hbin(stm_h[i])], 1);
}

// ---- 2: threshold + pad + top-M compaction + tie-break (1 block) -----------
__global__ void k_prep(const float* __restrict__ fat, float* __restrict__ oF,
                       const float* __restrict__ h, const int* __restrict__ act) {
    __shared__ int s[1024];
    __shared__ int sT, sCnt, ssel, sbnd;
    int t = threadIdx.x;
    int base = NBIN - 1 - 4 * t;
    int h0 = g_hist[base], h1 = g_hist[base-1], h2 = g_hist[base-2], h3 = g_hist[base-3];
    g_hist[base] = 0; g_hist[base-1] = 0; g_hist[base-2] = 0; g_hist[base-3] = 0;
    int sum = h0 + h1 + h2 + h3;
    s[t] = sum;
    if (t == 0) { ssel = 0; sbnd = 0; }
    __syncthreads();
    for (int off = 1; off < 1024; off <<= 1) {
        int v = s[t], a2 = (t >= off) ? s[t - off] : 0;
        __syncthreads(); s[t] = v + a2; __syncthreads();
    }
    int c = s[t] - sum;
    int hh[4] = {h0, h1, h2, h3};
    #pragma unroll
    for (int q = 0; q < 4; ++q) {
        if (c < TOP_M && c + hh[q] >= TOP_M) { sT = base - q; sCnt = c; }
        c += hh[q];
    }
    int n_act = g_scal[4];
    for (int idx = t; idx < 128 * 64; idx += 1024) {
        g_lknC[(size_t)n_act * 64 + idx] = 0.0f;
        g_lknB[(size_t)n_act * 64 + idx] = __float2bfloat16(0.0f);
    }
    if (t < 128) g_ajinv[n_act + t] = 0u;
    if (t == 0) {
        g_scal[5] = (n_act + 127) >> 7;
        oF[0] = 0.2f * fat[0];
    }
    __syncthreads();
    int T = sT;
    for (int b2 = 0; b2 < N_STM; b2 += 4096) {
        int ia[4]; float ha[4];
        #pragma unroll
        for (int q = 0; q < 4; ++q) {
            int i = b2 + q * 1024 + t;
            ia[q] = act[i]; ha[q] = h[i];
        }
        #pragma unroll
        for (int q = 0; q < 4; ++q) {
            if (ia[q] > 0) {
                int bn = hbin(ha[q]);
                int i = b2 + q * 1024 + t;
                if (bn > T)       g_sel[atomicAdd(&ssel, 1)] = i;
                else if (bn == T) g_boundary[atomicAdd(&sbnd, 1)] = i;
            }
        }
    }
    __syncthreads();
    int B = sbnd, need = TOP_M - sCnt;
    for (int cc = t; cc < B; cc += 1024) {
        int i = g_boundary[cc];
        unsigned long long k = stm_key(i, h[i]);
        int r = 0;
        for (int q = 0; q < B; ++q) {
            int i2 = g_boundary[q];
            r += (stm_key(i2, h[i2]) > k);
        }
        if (r < need) g_sel[atomicAdd(&ssel, 1)] = i;
    }
    __syncthreads();
    if (t == 0) g_scal[4] = 0;   // restore for graph replay
}

// ---- 3: projection + kp normalize (fp32 + bf16) ----------------------------
__global__ void k_proj(const float* __restrict__ stm_K, const float* __restrict__ stm_h,
                       const float* __restrict__ W, const float* __restrict__ b) {
    int m = blockIdx.x, c = threadIdx.x;
    __shared__ float sK[16];
    __shared__ float ws[2];
    int s = g_sel[m];
    if (c < 16) sK[c] = stm_K[(size_t)s * 16 + c];
    __syncthreads();
    float acc = b[c];
    #pragma unroll
    for (int k = 0; k < 16; ++k) acc = fmaf(sK[k], W[k * 64 + c], acc);
    float sq = acc * acc;
    #pragma unroll
    for (int off = 16; off; off >>= 1) sq += __shfl_xor_sync(0xFFFFFFFFu, sq, off);
    if ((c & 31) == 0) ws[c >> 5] = sq;
    __syncthreads();
    float kpv = acc / (sqrtf(ws[0] + ws[1]) + 1e-8f);
    g_Kproj[m * 64 + c] = acc;
    g_kpN[m * 64 + c] = kpv;
    g_kpB[m * 64 + c] = __float2bfloat16(kpv);
    if (c == 0) g_omega[m] = 0.05f * stm_h[s];
}

// ---- 4 (S1): bf16 HMMA screen: per-(m,stage) max + per-m global max --------
// CTA 64m x 128j, 8 warps (2 m-warp x 4 n-warp). smem rows stride 72 bf16
// (144B = 36 banks -> frag quad-rows hit distinct bank groups).
__global__ void __launch_bounds__(256) k_simsT() {
    __shared__ __align__(16) __nv_bfloat16 sA[64 * 72];
    __shared__ __align__(16) __nv_bfloat16 sB[128 * 72];
    __shared__ unsigned s_max[64];
    const int tid = threadIdx.x, wid = tid >> 5, l = tid & 31;
    const int warp_m = wid >> 2, warp_n = wid & 3;
    const int m0 = blockIdx.x * 64;
    const int ns = g_scal[5];
    unsigned* sA32 = (unsigned*)sA;
    unsigned* sB32 = (unsigned*)sB;

    // A fill: 64 rows x 32 u32
    {
        const unsigned* src = (const unsigned*)(g_kpB + (size_t)m0 * 64);
        #pragma unroll
        for (int i = 0; i < 8; ++i) {
            int idx = tid + i * 256;
            int row = idx >> 5, cu = idx & 31;
            sA32[row * 36 + cu] = src[idx];
        }
    }

    float runmax = -3.0f;

    for (int t = blockIdx.y; t < ns; t += (int)gridDim.y) {
        __syncthreads();   // prior frag reads + s_max reads done
        {
            const unsigned* src = (const unsigned*)(g_lknB + (size_t)t * 128 * 64);
            #pragma unroll
            for (int i = 0; i < 16; ++i) {
                int idx = tid + i * 256;
                int row = idx >> 5, cu = idx & 31;
                sB32[row * 36 + cu] = __ldg(&src[idx]);
            }
        }
        if (tid < 64) s_max[tid] = 0u;
        __syncthreads();

        float acc[2][4][4];
        #pragma unroll
        for (int i = 0; i < 2; ++i)
            #pragma unroll
            for (int q = 0; q < 4; ++q)
                #pragma unroll
                for (int r = 0; r < 4; ++r) acc[i][q][r] = 0.0f;

        #pragma unroll
        for (int kk = 0; kk < 64; kk += 16) {
            unsigned a[2][4], b[4][2];
            int kc = kk + 2 * (l & 3);
            #pragma unroll
            for (int i = 0; i < 2; ++i) {
                int r0 = warp_m * 32 + i * 16 + (l >> 2);
                a[i][0] = sA32[(r0 * 72 + kc) >> 1];
                a[i][1] = sA32[((r0 + 8) * 72 + kc) >> 1];
                a[i][2] = sA32[(r0 * 72 + kc + 8) >> 1];
                a[i][3] = sA32[((r0 + 8) * 72 + kc + 8) >> 1];
            }
            #pragma unroll
            for (int q = 0; q < 4; ++q) {
                int rb = warp_n * 32 + q * 8 + (l >> 2);
                b[q][0] = sB32[(rb * 72 + kc) >> 1];
                b[q][1] = sB32[(rb * 72 + kc + 8) >> 1];
            }
            #pragma unroll
            for (int i = 0; i < 2; ++i)
                #pragma unroll
                for (int q = 0; q < 4; ++q)
                    mma16816(acc[i][q], a[i], b[q]);
        }

        // per-m max: rows (base + l/4) and (base + l/4 + 8)
        #pragma unroll
        for (int i = 0; i < 2; ++i) {
            float t0 = -3.0f, t1 = -3.0f;
            #pragma unroll
            for (int q = 0; q < 4; ++q) {
                t0 = fmaxf(t0, fmaxf(acc[i][q][0], acc[i][q][1]));
                t1 = fmaxf(t1, fmaxf(acc[i][q][2], acc[i][q][3]));
            }
            t0 = fmaxf(t0, __shfl_xor_sync(0xFFFFFFFFu, t0, 1));
            t0 = fmaxf(t0, __shfl_xor_sync(0xFFFFFFFFu, t0, 2));
            t1 = fmaxf(t1, __shfl_xor_sync(0xFFFFFFFFu, t1, 1));
            t1 = fmaxf(t1, __shfl_xor_sync(0xFFFFFFFFu, t1, 2));
            if ((l & 3) == 0) {
                int r0 = warp_m * 32 + i * 16 + (l >> 2);
                atomicMax(&s_max[r0], fmono(t0));
                atomicMax(&s_max[r0 + 8], fmono(t1));
            }
        }
        __syncthreads();
        if (tid < 64) {
            float v = funmono(s_max[tid]);
            g_smax[(size_t)(m0 + tid) * NSMAX + t] = v;
            runmax = fmaxf(runmax, v);
        }
    }
    if (tid < 64) atomicMax(&g_gmaxU[m0 + tid], fmono(runmax));
}

// ---- 5 (S2): exact fp32 recheck of candidate stages -> g_best --------------
__global__ void k_exact() {
    int wid = threadIdx.x >> 5, lane = threadIdx.x & 31;
    int m = blockIdx.x * 8 + wid;
    int ns = g_scal[5];
    float thr = funmono(g_gmaxU[m]) - 0.02f;
    float4 kp4[16];
    const float4* kpr = reinterpret_cast<const float4*>(g_kpN + m * 64);
    #pragma unroll
    for (int i = 0; i < 16; ++i) kp4[i] = kpr[i];
    unsigned long long best = 0ull;
    for (int t = 0; t < ns; ++t) {
        if (g_smax[(size_t)m * NSMAX + t] < thr) continue;
        #pragma unroll
        for (int q = 0; q < 4; ++q) {
            int j = t * 128 + lane + q * 32;
            const float4* br = reinterpret_cast<const float4*>(g_lknC + (size_t)j * 64);
            float dot = 0.f;
            #pragma unroll
            for (int i = 0; i < 16; ++i) {
                float4 b4 = br[i];
                dot = fmaf(kp4[i].x, b4.x, dot);
                dot = fmaf(kp4[i].y, b4.y, dot);
                dot = fmaf(kp4[i].z, b4.z, dot);
                dot = fmaf(kp4[i].w, b4.w, dot);
            }
            unsigned long long pk =
                ((unsigned long long)fmono(dot) << 32) | g_ajinv[j];
            if (pk > best) best = pk;
        }
    }
    #pragma unroll
    for (int off = 16; off; off >>= 1) {
        unsigned long long o = __shfl_xor_sync(0xFFFFFFFFu, best, off);
        if (o > best) best = o;
    }
    if (lane == 0) { g_best[m] = best; g_gmaxU[m] = 0u; }  // reset for replay
}

// ---- 6: stm_V norm clip -----------------------------------------------------
__global__ void k_stmv(const float* __restrict__ stm_V, float* __restrict__ oSV) {
    int w = threadIdx.x >> 5, lane = threadIdx.x & 31;
    size_t row = (size_t)blockIdx.x * 8 + w;
    float4 v = reinterpret_cast<const float4*>(stm_V)[row * 32 + lane];
    float sq = v.x*v.x + v.y*v.y + v.z*v.z + v.w*v.w;
    #pragma unroll
    for (int off = 16; off; off >>= 1) sq += __shfl_xor_sync(0xFFFFFFFFu, sq, off);
    float sc = fminf(1.0f, 2.0f / (sqrtf(sq) + 1e-8f));
    reinterpret_cast<float4*>(oSV)[row * 32 + lane] =
        make_float4(v.x*sc, v.y*sc, v.z*sc, v.w*sc);
}

// ---- 7: first TOP_M inactive slots ------------------------------------------
__global__ void k_freeslots(const int* __restrict__ act) {
    int t = threadIdx.x, w = t >> 5, lane = t & 31;
    __shared__ int wcnt[32];
    int running = 0;
    for (int tile = 0; tile < 64 && running < TOP_M; ++tile) {
        int i = tile * 1024 + t;
        int inact = (act[i] == 0);
        unsigned bal = __ballot_sync(0xFFFFFFFFu, inact);
        if (lane == 0) wcnt[w] = __popc(bal);
        __syncthreads();
        int pre = 0, total = 0;
        #pragma unroll
        for (int x = 0; x < 32; ++x) {
            int cx = wcnt[x];
            if (x < w) pre += cx;
            total += cx;
        }
        int pos = running + pre + __popc(bal & ((1u << lane) - 1));
        if (inact && pos < TOP_M) g_free[pos] = i;
        running += total;
        __syncthreads();
    }
}

// ---- 8: matched scatter-add -------------------------------------------------
__global__ void k_matched(const float* __restrict__ stm_V, const float* __restrict__ stm_e,
                          const float* __restrict__ stm_h,
                          float* __restrict__ oK, float* __restrict__ oV,
                          float* __restrict__ oe, float* __restrict__ oh) {
    int m = blockIdx.x, c = threadIdx.x;
    unsigned long long p = g_best[m];
    float sim = funmono((unsigned)(p >> 32));
    int j = (int)(0xFFFFFFFFu - (unsigned)(p & 0xFFFFFFFFull));
    bool matched = (sim >= 0.5f);
    int s = g_sel[m];
    float om = g_omega[m];
    if (c == 0) {
        g_unm[m] = matched ? 0 : 1;
        g_key[m] = stm_key(s, stm_h[s]);
        if (matched) atomicAdd(&oh[j], om);
    }
    if (matched) {
        atomicAdd(&oK[(size_t)j * 64 + c], om * g_Kproj[m * 64 + c]);
        atomicAdd(&oV[(size_t)j * 128 + c], om * stm_V[(size_t)s * 128 + c]);
        atomicAdd(&oV[(size_t)j * 128 + 64 + c], om * stm_V[(size_t)s * 128 + 64 + c]);
        if (c < 4) atomicAdd(&oe[(size_t)j * 4 + c], om * stm_e[(size_t)s * 4 + c]);
    }
}

// ---- 9: rank unmatched (h desc, idx asc) -------------------------------------
__global__ void k_rank() {
    __shared__ unsigned long long sk[TOP_M];
    __shared__ unsigned char su[TOP_M];
    int t = threadIdx.x;
    for (int i = t; i < TOP_M; i += 256) { sk[i] = g_key[i]; su[i] = (unsigned char)g_unm[i]; }
    __syncthreads();
    int m = blockIdx.x * 256 + t;
    if (g_unm[m]) {
        unsigned long long k = sk[m];
        int r = 0;
        for (int i = 0; i < TOP_M; ++i) r += (su[i] && sk[i] > k);
        g_rank[m] = r;
    }
}

// ---- 10: unmatched fresh-slot writes -----------------------------------------
__global__ void k_unmatch(const float* __restrict__ stm_V, const float* __restrict__ stm_e,
                          float* __restrict__ oK, float* __restrict__ oV,
                          float* __restrict__ oe, float* __restrict__ oh) {
    int m = blockIdx.x;
    if (!g_unm[m]) return;
    int slot = g_free[g_rank[m]], c = threadIdx.x, s = g_sel[m];
    oK[(size_t)slot * 64 + c] = g_Kproj[m * 64 + c];
    oV[(size_t)slot * 128 + c] = stm_V[(size_t)s * 128 + c];
    oV[(size_t)slot * 128 + 64 + c] = stm_V[(size_t)s * 128 + 64 + c];
    if (c < 4) oe[(size_t)slot * 4 + c] = stm_e[(size_t)s * 4 + c];
    if (c == 0) oh[slot] = g_omega[m];
}

// ---- fused 3D gaussian blur + merge (branchless, div-free) -------------------
#define BLUR_SMEM ((10368 + 10368) * 4)   // 82944 B
__global__ void __launch_bounds__(256) k_blurAll(const float* __restrict__ stm_t,
                                                 const float* __restrict__ ltm_t,
                                                 float* __restrict__ oT) {
    extern __shared__ float p[];
    float* p0 = p;
    float* p0c = p + 576;
    float* p1 = p + 10368;
    float w[7], inv; gw(w, inv);
    int tid = threadIdx.x;
    int plane = blockIdx.x;
    int c = plane / 96, d = plane % 96;
    size_t cbase = (size_t)c * 96 * 9216;

    for (int i = tid; i < 576; i += 256) { p0[i] = 0.0f; p0[9792 + i] = 0.0f; }
    for (int i = tid; i < 1152; i += 256) {
        int row = i / 12, cc = i - row * 12;
        p1[row * 108 + (cc < 6 ? cc : 96 + cc)] = 0.0f;
    }

    float4 acc[9];
    #pragma unroll
    for (int e = 0; e < 9; ++e) acc[e] = make_float4(0.f, 0.f, 0.f, 0.f);
    #pragma unroll
    for (int t = -6; t <= 6; ++t) {
        int dd = d + t;
        if (dd < 0 || dd >= 96) continue;
        float ww = w[t < 0 ? -t : t];
        const float4* src = reinterpret_cast<const float4*>(stm_t + cbase + (size_t)dd * 9216);
        #pragma unroll
        for (int e = 0; e < 9; ++e) {
            float4 v = src[tid + e * 256];
            acc[e].x = fmaf(v.x, ww, acc[e].x);
            acc[e].y = fmaf(v.y, ww, acc[e].y);
            acc[e].z = fmaf(v.z, ww, acc[e].z);
            acc[e].w = fmaf(v.w, ww, acc[e].w);
        }
    }
    float4* d0 = reinterpret_cast<float4*>(p0c);
    #pragma unroll
    for (int e = 0; e < 9; ++e) {
        float4 v = acc[e];
        d0[tid + e * 256] = make_float4(v.x * inv, v.y * inv, v.z * inv, v.w * inv);
    }
    __syncthreads();

    {
        int h = tid / 96;
        int x = tid - h * 96;
        for (int i = tid; i < 9216; i += 256) {
            float a2 = p0c[i] * w[0];
            #pragma unroll
            for (int t = 1; t < 7; ++t)
                a2 += (p0c[i - t * 96] + p0c[i + t * 96]) * w[t];
            p1[h * 108 + 6 + x] = a2 * inv;
            x += 64; h += 2;
            if (x >= 96) { x -= 96; h += 1; }
        }
    }
    __syncthreads();

    {
        float xi = (c == 0) ? 0.005f : 0.003f;
        size_t base = cbase + (size_t)d * 9216;
        int h = tid / 96;
        int x = tid - h * 96;
        for (int i = tid; i < 9216; i += 256) {
            const float* row = p1 + h * 108 + 6 + x;
            float a2 = row[0] * w[0];
            #pragma unroll
            for (int t = 1; t < 7; ++t)
                a2 += (row[-t] + row[t]) * w[t];
            oT[base + i] = ltm_t[base + i] + xi * (a2 * inv);
            x += 64; h += 2;
            if (x >= 96) { x -= 96; h += 1; }
        }
    }
}

extern "C" void kernel_launch(void* const* d_in, const int* in_sizes, int n_in,
                              void* d_out, int out_size) {
    (void)in_sizes; (void)n_in; (void)out_size;
    const float* stm_K   = (const float*)d_in[0];
    const float* stm_V   = (const float*)d_in[1];
    const float* stm_e   = (const float*)d_in[2];
    const float* stm_h   = (const float*)d_in[3];
    const float* ltm_K   = (const float*)d_in[4];
    const float* ltm_V   = (const float*)d_in[5];
    const float* ltm_e   = (const float*)d_in[6];
    const float* ltm_h   = (const float*)d_in[7];
    const float* W       = (const float*)d_in[8];
    const float* b       = (const float*)d_in[9];
    const float* stm_t   = (const float*)d_in[10];
    const float* ltm_t   = (const float*)d_in[11];
    const float* fatigue = (const float*)d_in[12];
    const int*   stm_act = (const int*)d_in[13];
    const int*   ltm_act = (const int*)d_in[14];

    float* out = (float*)d_out;
    float* oK  = out;                 // 65536*64
    float* oV  = out + 4194304;       // 65536*128
    float* oe  = out + 12582912;      // 65536*4
    float* oh  = out + 12845056;      // 65536
    float* oSV = out + 12910592;      // 65536*128
    float* oT  = out + 21299200;      // 5*96^3
    float* oF  = out + 25722880;      // 1

    static cudaStream_t sB = 0, sC = 0, sD = 0;
    static cudaEvent_t eR = 0, eB = 0, eC = 0, eD = 0;
    static bool init_done = false;
    if (!init_done) {
        cudaFuncSetAttribute(k_blurAll, cudaFuncAttributeMaxDynamicSharedMemorySize, BLUR_SMEM);
        cudaStreamCreateWithFlags(&sB, cudaStreamNonBlocking);
        cudaStreamCreateWithFlags(&sC, cudaStreamNonBlocking);
        cudaStreamCreateWithFlags(&sD, cudaStreamNonBlocking);
        cudaEventCreateWithFlags(&eR, cudaEventDisableTiming);
        cudaEventCreateWithFlags(&eB, cudaEventDisableTiming);
        cudaEventCreateWithFlags(&eC, cudaEventDisableTiming);
        cudaEventCreateWithFlags(&eD, cudaEventDisableTiming);
        init_done = true;
    }

    // fork
    cudaEventRecord(eR, 0);
    cudaStreamWaitEvent(sB, eR, 0);
    cudaStreamWaitEvent(sC, eR, 0);
    cudaStreamWaitEvent(sD, eR, 0);

    // critical path first (k_simsT = launch #4 for ncu)
    k_histlkn<<<16384, 256>>>(ltm_K, ltm_act, stm_h, stm_act);
    k_prep<<<1, 1024>>>(fatigue, oF, stm_h, stm_act);
    k_proj<<<2048, 64>>>(stm_K, stm_h, W, b);
    k_simsT<<<dim3(32, 9), 256>>>();
    k_exact<<<256, 256>>>();

    // side chain B: base copy + free slot list
    k_copy<<<12608, 256, 0, sB>>>((const float4*)ltm_K, (const float4*)ltm_V,
                                  (const float4*)ltm_e, (const float4*)ltm_h,
                                  (float4*)oK);
    k_freeslots<<<1, 1024, 0, sB>>>(ltm_act);
    cudaEventRecord(eB, sB);

    // side chain C: stm_V clip
    k_stmv<<<8192, 256, 0, sC>>>(stm_V, oSV);
    cudaEventRecord(eC, sC);

    // side chain D: fused terrain blur + merge
    k_blurAll<<<480, 256, BLUR_SMEM, sD>>>(stm_t, ltm_t, oT);
    cudaEventRecord(eD, sD);

    // tail of critical path
    cudaStreamWaitEvent(0, eB, 0);
    k_matched<<<2048, 64>>>(stm_V, stm_e, stm_h, oK, oV, oe, oh);
    k_rank<<<8, 256>>>();
    k_unmatch<<<2048, 64>>>(stm_V, stm_e, oK, oV, oe, oh);

    // join remaining side chains
    cudaStreamWaitEvent(0, eC, 0);
    cudaStreamWaitEvent(0, eD, 0);
}